// round 2
// baseline (speedup 1.0000x reference)
#include <cuda_runtime.h>
#include <cuda_bf16.h>
#include <math.h>

// Problem constants
#define B   4
#define C   256
#define H   64
#define W   64
#define O   256
#define K   9           // 3x3
#define HW  4096        // H*W
#define CK  2304        // C*K
#define NPIX 16384      // B*H*W

// ---------------- scratch (__device__ globals; no allocs allowed) -------------
__device__ float  g_om[B * 27 * HW];          // offset-conv accumulator (27 ch)
__device__ float  g_womT[256 * 9 * 28];       // repacked offset weights [c][j][oc(pad28)]
__device__ float4 g_spw[B * K * HW];          // per-(b,k,h,w): 4 folded bilinear weights
__device__ int4   g_spc[B * K * HW];          // per-(b,k,h,w): y0*64, y1*64, x0, x1 (clamped)

// ---------------- kernel 0: zero the offset-conv accumulator ------------------
__global__ void zero_om_kernel() {
    int i = blockIdx.x * blockDim.x + threadIdx.x;
    g_om[i] = 0.0f;
}

// ---------------- kernel 1: repack w_om  [oc][c][j] -> [c][j][oc pad 28] ------
__global__ void repack_wom_kernel(const float* __restrict__ w_om) {
    int d = blockIdx.x * blockDim.x + threadIdx.x;   // < 256*252
    int c = d / 252;
    int r = d - c * 252;
    int j = r / 28;
    int oc = r - j * 28;
    float v = (oc < 27) ? w_om[oc * CK + c * 9 + j] : 0.0f;
    g_womT[d] = v;
}

// ---------------- kernel 2: offset conv (27ch 3x3, pad 1), C split 4 ways -----
// grid: (h=64, b=4, cseg=4), block: 64 threads (one output row)
__global__ void offset_conv_kernel(const float* __restrict__ x) {
    __shared__ __align__(16) float xs[3][66];
    __shared__ __align__(16) float ws[9 * 28];

    const int h  = blockIdx.x;
    const int b  = blockIdx.y;
    const int c0 = blockIdx.z * 64;
    const int w  = threadIdx.x;

    float acc[28];
    #pragma unroll
    for (int i = 0; i < 28; ++i) acc[i] = 0.0f;

    // horizontal halo zeros (never overwritten)
    if (w < 6) xs[w >> 1][(w & 1) * 65] = 0.0f;

    for (int c = c0; c < c0 + 64; ++c) {
        __syncthreads();
        const float* xp = x + (((b << 8) + c) << 12);
        #pragma unroll
        for (int r = 0; r < 3; ++r) {
            int hr = h + r - 1;
            xs[r][w + 1] = (hr >= 0 && hr < H) ? xp[hr * W + w] : 0.0f;
        }
        for (int i = w; i < 252; i += 64) ws[i] = g_womT[c * 252 + i];
        __syncthreads();

        float xr[9];
        #pragma unroll
        for (int ky = 0; ky < 3; ++ky)
            #pragma unroll
            for (int kx = 0; kx < 3; ++kx)
                xr[ky * 3 + kx] = xs[ky][w + kx];

        const float4* ws4 = reinterpret_cast<const float4*>(ws);
        #pragma unroll
        for (int j = 0; j < 9; ++j) {
            float xv = xr[j];
            #pragma unroll
            for (int q = 0; q < 7; ++q) {
                float4 wv = ws4[j * 7 + q];
                acc[q * 4 + 0] += xv * wv.x;
                acc[q * 4 + 1] += xv * wv.y;
                acc[q * 4 + 2] += xv * wv.z;
                acc[q * 4 + 3] += xv * wv.w;
            }
        }
    }

    float* op = g_om + (b * 27) * HW + h * W + w;
    #pragma unroll
    for (int oc = 0; oc < 27; ++oc) atomicAdd(op + oc * HW, acc[oc]);
}

// ---------------- kernel 3: offsets/mask -> sampling params -------------------
// one thread per (b, k, h, w) : B*K*HW = 147456 threads
__global__ void params_kernel(const float* __restrict__ b_om) {
    int idx = blockIdx.x * blockDim.x + threadIdx.x;   // < 147456
    int b  = idx / (K * HW);
    int r  = idx - b * (K * HW);
    int k  = r >> 12;
    int hw = r & 4095;
    int h  = hw >> 6;
    int w  = hw & 63;

    const float* omb = g_om + b * 27 * HW;
    float off_y = omb[(2 * k    ) * HW + hw] + b_om[2 * k];
    float off_x = omb[(2 * k + 1) * HW + hw] + b_om[2 * k + 1];
    float mval  = omb[(18 + k   ) * HW + hw] + b_om[18 + k];
    float m = 1.0f / (1.0f + expf(-mval));

    float py = (float)(h - 1 + k / 3) + off_y;
    float px = (float)(w - 1 + k % 3) + off_x;

    float y0f = floorf(py), x0f = floorf(px);
    float ly = py - y0f, lx = px - x0f;
    int y0 = (int)y0f, x0 = (int)x0f;
    int y1 = y0 + 1,   x1 = x0 + 1;

    float vy0 = (y0 >= 0 && y0 < H) ? 1.0f : 0.0f;
    float vy1 = (y1 >= 0 && y1 < H) ? 1.0f : 0.0f;
    float vx0 = (x0 >= 0 && x0 < W) ? 1.0f : 0.0f;
    float vx1 = (x1 >= 0 && x1 < W) ? 1.0f : 0.0f;

    float4 wv;
    wv.x = (1.0f - ly) * (1.0f - lx) * m * vy0 * vx0;
    wv.y = (1.0f - ly) * lx          * m * vy0 * vx1;
    wv.z = ly * (1.0f - lx)          * m * vy1 * vx0;
    wv.w = ly * lx                   * m * vy1 * vx1;

    int4 cv;
    cv.x = min(max(y0, 0), H - 1) * W;
    cv.y = min(max(y1, 0), H - 1) * W;
    cv.z = min(max(x0, 0), W - 1);
    cv.w = min(max(x1, 0), W - 1);

    g_spw[idx] = wv;
    g_spc[idx] = cv;
}

// ---------------- kernel 4: fused gather + GEMM -------------------------------
// block: 256 threads (thread = output channel o), pixel tile = 32 consecutive px
// grid: NPIX/32 = 512 blocks
__global__ void __launch_bounds__(256, 2)
dcn_gemm_kernel(const float* __restrict__ x,
                const float* __restrict__ weight,
                const float* __restrict__ bias,
                float* __restrict__ out) {
    __shared__ __align__(16) float4 WtS[8][256];    // 32 ck (as 8 float4) x 256 o
    __shared__ __align__(16) float  csS[32][36];    // 32 px x 32 ck (+4 pad)
    __shared__ __align__(16) float4 spw[K][32];
    __shared__ __align__(16) int4   spc[K][32];

    const int tid  = threadIdx.x;
    const int pix0 = blockIdx.x << 5;
    const int b    = pix0 >> 12;
    const int hw0  = pix0 & 4095;

    // FIX: 288 entries staged by 256 threads -> strided loop (was `if (tid<288)`,
    // leaving k=8 row uninitialized -> wild LDG indices -> addr-space trap)
    for (int s = tid; s < K * 32; s += 256) {
        int k = s >> 5, p = s & 31;
        int gi = (b * K + k) * HW + hw0 + p;
        spw[k][p] = g_spw[gi];
        spc[k][p] = g_spc[gi];
    }
    __syncthreads();

    float acc[32];
    #pragma unroll
    for (int p = 0; p < 32; ++p) acc[p] = 0.0f;

    const float* xb = x + (b << 20);   // b * C * HW

    for (int ck0 = 0; ck0 < CK; ck0 += 32) {
        // stage weight tile: thread t loads o=t's 32 consecutive ck as 8 float4
        const float4* wp = reinterpret_cast<const float4*>(weight + tid * CK + ck0);
        #pragma unroll
        for (int j4 = 0; j4 < 8; ++j4) WtS[j4][tid] = wp[j4];

        // stage cols tile: 32 px x 32 ck samples; lanes = consecutive pixels
        #pragma unroll
        for (int i = 0; i < 4; ++i) {
            int s = tid + (i << 8);
            int p = s & 31;
            int j = s >> 5;
            int ck = ck0 + j;
            int c  = ck / 9;
            int k  = ck - c * 9;
            float4 ww = spw[k][p];
            int4   cc = spc[k][p];
            const float* xc = xb + (c << 12);
            float v = ww.x * xc[cc.x + cc.z] + ww.y * xc[cc.x + cc.w]
                    + ww.z * xc[cc.y + cc.z] + ww.w * xc[cc.y + cc.w];
            csS[p][j] = v;
        }
        __syncthreads();

        #pragma unroll
        for (int j4 = 0; j4 < 8; ++j4) {
            float4 w4 = WtS[j4][tid];
            #pragma unroll
            for (int p = 0; p < 32; ++p) {
                float4 c4 = *reinterpret_cast<const float4*>(&csS[p][j4 << 2]);
                acc[p] = fmaf(w4.x, c4.x, acc[p]);
                acc[p] = fmaf(w4.y, c4.y, acc[p]);
                acc[p] = fmaf(w4.z, c4.z, acc[p]);
                acc[p] = fmaf(w4.w, c4.w, acc[p]);
            }
        }
        __syncthreads();
    }

    const float bz = bias[tid];
    float* op = out + (b << 20) + (tid << 12) + hw0;
    #pragma unroll
    for (int p4 = 0; p4 < 8; ++p4) {
        float4 v = make_float4(acc[p4 * 4 + 0] + bz, acc[p4 * 4 + 1] + bz,
                               acc[p4 * 4 + 2] + bz, acc[p4 * 4 + 3] + bz);
        *reinterpret_cast<float4*>(op + (p4 << 2)) = v;
    }
}

// ---------------- launch ------------------------------------------------------
extern "C" void kernel_launch(void* const* d_in, const int* in_sizes, int n_in,
                              void* d_out, int out_size) {
    const float* x      = (const float*)d_in[0];   // (4,256,64,64)
    const float* w_om   = (const float*)d_in[1];   // (27,256,3,3)
    const float* b_om   = (const float*)d_in[2];   // (27,)
    const float* weight = (const float*)d_in[3];   // (256,256,3,3)
    const float* bias   = (const float*)d_in[4];   // (256,)
    float* out = (float*)d_out;                    // (4,256,64,64)

    zero_om_kernel<<<432, 1024>>>();                       // 442368 elems
    repack_wom_kernel<<<63, 1024>>>(w_om);                 // 64512 elems
    offset_conv_kernel<<<dim3(64, 4, 4), 64>>>(x);
    params_kernel<<<144, 1024>>>(b_om);                    // 147456 threads
    dcn_gemm_kernel<<<512, 256>>>(x, weight, bias, out);
}

// round 4
// speedup vs baseline: 1.3558x; 1.3558x over previous
#include <cuda_runtime.h>
#include <cuda_bf16.h>
#include <math.h>
#include <cstdint>

// Problem constants
#define B   4
#define C   256
#define H   64
#define W   64
#define O   256
#define K   9           // 3x3
#define HW  4096        // H*W
#define CK  2304        // C*K
#define KP  4608        // 2*CK (hi | lo)
#define NPIX 16384      // B*H*W

// GEMM config
#define KC      64      // K elems per chunk (bf16) = 128B rows
#define NCHUNK  108     // 3 passes x (2304/64)
#define STG     4       // cp.async pipeline stages
#define STAGE_BYTES 32768   // A 16KB + B 16KB
#define SMEM_DYN (1024 + STG * STAGE_BYTES)

// ---------------- scratch (__device__ globals; no allocs allowed) -------------
__device__ float  g_om[B * 27 * HW];
__device__ float  g_womT[256 * 9 * 28];
__device__ float4 g_spw[B * K * HW];
__device__ int4   g_spc[B * K * HW];
__device__ __nv_bfloat16 g_wsplit[O * KP];        // [o][hi(2304) | lo(2304)]
__device__ __nv_bfloat16 g_cols[(size_t)NPIX * KP]; // [px][hi(2304) | lo(2304)]

// ---------------- PTX helpers -------------------------------------------------
__device__ __forceinline__ uint32_t smem_u32(const void* p) {
    uint32_t a;
    asm("{ .reg .u64 t; cvta.to.shared.u64 t, %1; cvt.u32.u64 %0, t; }" : "=r"(a) : "l"(p));
    return a;
}
__device__ __forceinline__ void cp16(uint32_t dst, const void* src) {
    asm volatile("cp.async.cg.shared.global [%0], [%1], 16;" :: "r"(dst), "l"(src) : "memory");
}
#define CP_COMMIT() asm volatile("cp.async.commit_group;" ::: "memory")
#define CP_WAIT2()  asm volatile("cp.async.wait_group 2;" ::: "memory")
#define CP_WAIT0()  asm volatile("cp.async.wait_group 0;" ::: "memory")

__device__ __forceinline__ uint32_t sw128(uint32_t off) { return off ^ ((off >> 3) & 0x70); }

__device__ __forceinline__ void ldsm_x4(uint32_t* r, uint32_t addr) {
    asm volatile("ldmatrix.sync.aligned.m8n8.x4.shared.b16 {%0,%1,%2,%3}, [%4];"
        : "=r"(r[0]), "=r"(r[1]), "=r"(r[2]), "=r"(r[3]) : "r"(addr));
}
__device__ __forceinline__ void mma16816(float* d, const uint32_t* a, const uint32_t* b) {
    asm volatile("mma.sync.aligned.m16n8k16.row.col.f32.bf16.bf16.f32 "
        "{%0,%1,%2,%3}, {%4,%5,%6,%7}, {%8,%9}, {%0,%1,%2,%3};"
        : "+f"(d[0]), "+f"(d[1]), "+f"(d[2]), "+f"(d[3])
        : "r"(a[0]), "r"(a[1]), "r"(a[2]), "r"(a[3]), "r"(b[0]), "r"(b[1]));
}

// ---------------- kernel 0: zero the offset-conv accumulator ------------------
__global__ void zero_om_kernel() {
    int i = blockIdx.x * blockDim.x + threadIdx.x;
    g_om[i] = 0.0f;
}

// ---------------- kernel 1: repack w_om  [oc][c][j] -> [c][j][oc pad 28] ------
__global__ void repack_wom_kernel(const float* __restrict__ w_om) {
    int d = blockIdx.x * blockDim.x + threadIdx.x;
    int c = d / 252;
    int r = d - c * 252;
    int j = r / 28;
    int oc = r - j * 28;
    float v = (oc < 27) ? w_om[oc * CK + c * 9 + j] : 0.0f;
    g_womT[d] = v;
}

// ---------------- kernel 1b: split main conv weights into bf16 hi/lo ----------
__global__ void wsplit_kernel(const float* __restrict__ weight) {
    int i = blockIdx.x * blockDim.x + threadIdx.x;   // < 256*2304
    float v = weight[i];
    __nv_bfloat16 hi = __float2bfloat16(v);
    __nv_bfloat16 lo = __float2bfloat16(v - __bfloat162float(hi));
    int o = i / CK, ck = i - o * CK;
    g_wsplit[o * KP + ck]      = hi;
    g_wsplit[o * KP + CK + ck] = lo;
}

// ---------------- kernel 2: offset conv (27ch 3x3, pad 1), C split 4 ways -----
__global__ void offset_conv_kernel(const float* __restrict__ x) {
    __shared__ __align__(16) float xs[3][66];
    __shared__ __align__(16) float ws[9 * 28];

    const int h  = blockIdx.x;
    const int b  = blockIdx.y;
    const int c0 = blockIdx.z * 64;
    const int w  = threadIdx.x;

    float acc[28];
    #pragma unroll
    for (int i = 0; i < 28; ++i) acc[i] = 0.0f;

    if (w < 6) xs[w >> 1][(w & 1) * 65] = 0.0f;

    for (int c = c0; c < c0 + 64; ++c) {
        __syncthreads();
        const float* xp = x + (((b << 8) + c) << 12);
        #pragma unroll
        for (int r = 0; r < 3; ++r) {
            int hr = h + r - 1;
            xs[r][w + 1] = (hr >= 0 && hr < H) ? xp[hr * W + w] : 0.0f;
        }
        for (int i = w; i < 252; i += 64) ws[i] = g_womT[c * 252 + i];
        __syncthreads();

        float xr[9];
        #pragma unroll
        for (int ky = 0; ky < 3; ++ky)
            #pragma unroll
            for (int kx = 0; kx < 3; ++kx)
                xr[ky * 3 + kx] = xs[ky][w + kx];

        const float4* ws4 = reinterpret_cast<const float4*>(ws);
        #pragma unroll
        for (int j = 0; j < 9; ++j) {
            float xv = xr[j];
            #pragma unroll
            for (int q = 0; q < 7; ++q) {
                float4 wv = ws4[j * 7 + q];
                acc[q * 4 + 0] += xv * wv.x;
                acc[q * 4 + 1] += xv * wv.y;
                acc[q * 4 + 2] += xv * wv.z;
                acc[q * 4 + 3] += xv * wv.w;
            }
        }
    }

    float* op = g_om + (b * 27) * HW + h * W + w;
    #pragma unroll
    for (int oc = 0; oc < 27; ++oc) atomicAdd(op + oc * HW, acc[oc]);
}

// ---------------- kernel 3: offsets/mask -> sampling params -------------------
__global__ void params_kernel(const float* __restrict__ b_om) {
    int idx = blockIdx.x * blockDim.x + threadIdx.x;
    int b  = idx / (K * HW);
    int r  = idx - b * (K * HW);
    int k  = r >> 12;
    int hw = r & 4095;
    int h  = hw >> 6;
    int w  = hw & 63;

    const float* omb = g_om + b * 27 * HW;
    float off_y = omb[(2 * k    ) * HW + hw] + b_om[2 * k];
    float off_x = omb[(2 * k + 1) * HW + hw] + b_om[2 * k + 1];
    float mval  = omb[(18 + k   ) * HW + hw] + b_om[18 + k];
    float m = 1.0f / (1.0f + expf(-mval));

    float py = (float)(h - 1 + k / 3) + off_y;
    float px = (float)(w - 1 + k % 3) + off_x;

    float y0f = floorf(py), x0f = floorf(px);
    float ly = py - y0f, lx = px - x0f;
    int y0 = (int)y0f, x0 = (int)x0f;
    int y1 = y0 + 1,   x1 = x0 + 1;

    float vy0 = (y0 >= 0 && y0 < H) ? 1.0f : 0.0f;
    float vy1 = (y1 >= 0 && y1 < H) ? 1.0f : 0.0f;
    float vx0 = (x0 >= 0 && x0 < W) ? 1.0f : 0.0f;
    float vx1 = (x1 >= 0 && x1 < W) ? 1.0f : 0.0f;

    float4 wv;
    wv.x = (1.0f - ly) * (1.0f - lx) * m * vy0 * vx0;
    wv.y = (1.0f - ly) * lx          * m * vy0 * vx1;
    wv.z = ly * (1.0f - lx)          * m * vy1 * vx0;
    wv.w = ly * lx                   * m * vy1 * vx1;

    int4 cv;
    cv.x = min(max(y0, 0), H - 1) * W;
    cv.y = min(max(y1, 0), H - 1) * W;
    cv.z = min(max(x0, 0), W - 1);
    cv.w = min(max(x1, 0), W - 1);

    g_spw[idx] = wv;
    g_spc[idx] = cv;
}

// ---------------- kernel 4: gather -> bf16 hi/lo im2col cols ------------------
// block: 256 threads, 32 px; warp lanes sweep ck (coalesced 64B writes)
__global__ void __launch_bounds__(256) gather_kernel(const float* __restrict__ x) {
    __shared__ __align__(16) float4 spw[K][32];
    __shared__ __align__(16) int4   spc[K][32];

    const int tid  = threadIdx.x;
    const int pix0 = blockIdx.x << 5;
    const int b    = pix0 >> 12;
    const int hw0  = pix0 & 4095;

    for (int s = tid; s < K * 32; s += 256) {
        int k = s >> 5, p = s & 31;
        int gi = (b * K + k) * HW + hw0 + p;
        spw[k][p] = g_spw[gi];
        spc[k][p] = g_spc[gi];
    }
    __syncthreads();

    const float* xb = x + (b << 20);
    const int wid = tid >> 5, lane = tid & 31;

    for (int t = wid; t < 32 * 72; t += 8) {
        int p  = t / 72;
        int g  = t - p * 72;
        int ck = g * 32 + lane;
        int c  = ck / 9;
        int k  = ck - c * 9;
        float4 ww = spw[k][p];
        int4   cc = spc[k][p];
        const float* xc = xb + (c << 12);
        float v = ww.x * xc[cc.x + cc.z] + ww.y * xc[cc.x + cc.w]
                + ww.z * xc[cc.y + cc.z] + ww.w * xc[cc.y + cc.w];
        __nv_bfloat16 hi = __float2bfloat16(v);
        __nv_bfloat16 lo = __float2bfloat16(v - __bfloat162float(hi));
        size_t base = (size_t)(pix0 + p) * KP;
        g_cols[base + ck]      = hi;
        g_cols[base + CK + ck] = lo;
    }
}

// ---------------- kernel 5: HMMA GEMM  D[o, px] = Wsplit x Cols^T -------------
// grid (128, 2): x = px tile (128 px), y = o tile (128 o). 256 threads (8 warps).
// warp tile 64(m) x 32(n): warps laid out 2(m) x 4(n).
__global__ void __launch_bounds__(256, 1)
gemm_kernel(const float* __restrict__ bias, float* __restrict__ out) {
    extern __shared__ __align__(16) char dyn_smem[];
    const uint32_t smem_base = smem_u32(dyn_smem);
    const uint32_t tile0 = (smem_base + 1023u) & ~1023u;   // 1024-aligned stages

    const int tid  = threadIdx.x;
    const int wid  = tid >> 5;
    const int lane = tid & 31;
    const int o_tile = blockIdx.y;            // 0..1
    const int pxb    = blockIdx.x << 7;       // 128 px per CTA

    const int wm = wid & 1;                   // 0..1  -> m offset 64*wm
    const int wn = wid >> 1;                  // 0..3  -> n offset 32*wn

    const __nv_bfloat16* wA = g_wsplit + (size_t)o_tile * 128 * KP;
    const __nv_bfloat16* cB = g_cols + (size_t)pxb * KP;

    // cp.async geometry: 128 rows x 8 segs of 16B per operand, 256 threads -> 4 each
    const int rL = tid >> 1;                 // 0..127 (two segs per thread per half)
    const int sL = (tid & 1) << 1;           // seg 0/2 base, +1 below

    auto load_chunk = [&](int j) {
        int st = j % STG;
        uint32_t sa = tile0 + st * STAGE_BYTES;
        uint32_t sb = sa + 16384;
        int p  = j / 36;
        int kc = (j - p * 36) * KC;
        int aoff = ((p == 2) ? CK : 0) + kc;
        int boff = ((p == 1) ? CK : 0) + kc;
        const __nv_bfloat16* wr = wA + (size_t)rL * KP + aoff;
        const __nv_bfloat16* cr = cB + (size_t)rL * KP + boff;
        #pragma unroll
        for (int q = 0; q < 2; ++q) {
            int sg = sL + q;
            cp16(sa + sw128((uint32_t)(rL * 128 + sg * 16)), wr + sg * 8);
            cp16(sb + sw128((uint32_t)(rL * 128 + sg * 16)), cr + sg * 8);
        }
        #pragma unroll
        for (int q = 0; q < 2; ++q) {
            int sg = sL + q + 4;
            cp16(sa + sw128((uint32_t)(rL * 128 + sg * 16)), wr + sg * 8);
            cp16(sb + sw128((uint32_t)(rL * 128 + sg * 16)), cr + sg * 8);
        }
        CP_COMMIT();
    };

    float acc[4][4][4];
    #pragma unroll
    for (int i = 0; i < 4; ++i)
        #pragma unroll
        for (int j = 0; j < 4; ++j)
            #pragma unroll
            for (int q = 0; q < 4; ++q) acc[i][j][q] = 0.0f;

    // ldmatrix per-lane geometry (offsets within a stage tile)
    const uint32_t aRow = (uint32_t)(wm * 64 + (lane & 15));    // + mf*16
    const uint32_t aCb  = (uint32_t)((lane >> 4) << 4);         // + kk*32
    const uint32_t bRow = (uint32_t)(wn * 32 + ((lane >> 4) << 3) + (lane & 7)); // + half*16
    const uint32_t bCb  = (uint32_t)(((lane >> 3) & 1) << 4);   // + kk*32

    load_chunk(0);
    load_chunk(1);
    load_chunk(2);

    for (int i = 0; i < NCHUNK; ++i) {
        CP_WAIT2();
        __syncthreads();
        if (i + STG - 1 < NCHUNK) load_chunk(i + STG - 1);

        int st = i % STG;
        uint32_t sa = tile0 + st * STAGE_BYTES;
        uint32_t sb = sa + 16384;

        #pragma unroll
        for (int kk = 0; kk < 4; ++kk) {
            uint32_t a[4][4], b[4][2];
            #pragma unroll
            for (int mf = 0; mf < 4; ++mf)
                ldsm_x4(a[mf], sa + sw128((aRow + mf * 16) * 128 + aCb + kk * 32));
            #pragma unroll
            for (int half = 0; half < 2; ++half) {
                uint32_t r[4];
                ldsm_x4(r, sb + sw128((bRow + half * 16) * 128 + bCb + kk * 32));
                b[2 * half][0] = r[0]; b[2 * half][1] = r[1];
                b[2 * half + 1][0] = r[2]; b[2 * half + 1][1] = r[3];
            }
            #pragma unroll
            for (int mf = 0; mf < 4; ++mf)
                #pragma unroll
                for (int nf = 0; nf < 4; ++nf)
                    mma16816(acc[mf][nf], a[mf], b[nf]);
        }
    }
    CP_WAIT0();

    // ---- epilogue: direct register -> gmem stores -----------------------------
    const int bb  = pxb >> 12;
    const int hw0 = pxb & 4095;
    const int oBase = o_tile * 128 + wm * 64 + (lane >> 2);
    const int nBase = hw0 + wn * 32 + (lane & 3) * 2;

    #pragma unroll
    for (int mf = 0; mf < 4; ++mf) {
        int o0 = oBase + mf * 16;
        float bz0 = __ldg(bias + o0);
        float bz8 = __ldg(bias + o0 + 8);
        float* op0 = out + (bb << 20) + (o0 << 12) + nBase;
        float* op8 = op0 + (8 << 12);
        #pragma unroll
        for (int nf = 0; nf < 4; ++nf) {
            float2 v0 = make_float2(acc[mf][nf][0] + bz0, acc[mf][nf][1] + bz0);
            float2 v1 = make_float2(acc[mf][nf][2] + bz8, acc[mf][nf][3] + bz8);
            *reinterpret_cast<float2*>(op0 + nf * 8) = v0;
            *reinterpret_cast<float2*>(op8 + nf * 8) = v1;
        }
    }
}

// ---------------- launch ------------------------------------------------------
extern "C" void kernel_launch(void* const* d_in, const int* in_sizes, int n_in,
                              void* d_out, int out_size) {
    const float* x      = (const float*)d_in[0];   // (4,256,64,64)
    const float* w_om   = (const float*)d_in[1];   // (27,256,3,3)
    const float* b_om   = (const float*)d_in[2];   // (27,)
    const float* weight = (const float*)d_in[3];   // (256,256,3,3)
    const float* bias   = (const float*)d_in[4];   // (256,)
    float* out = (float*)d_out;                    // (4,256,64,64)

    cudaFuncSetAttribute(gemm_kernel, cudaFuncAttributeMaxDynamicSharedMemorySize, SMEM_DYN);

    zero_om_kernel<<<432, 1024>>>();
    repack_wom_kernel<<<63, 1024>>>(w_om);
    wsplit_kernel<<<576, 1024>>>(weight);
    offset_conv_kernel<<<dim3(64, 4, 4), 64>>>(x);
    params_kernel<<<144, 1024>>>(b_om);
    gather_kernel<<<512, 256>>>(x);
    gemm_kernel<<<dim3(128, 2), 256, SMEM_DYN>>>(bias, out);
}

// round 5
// speedup vs baseline: 2.6020x; 1.9191x over previous
#include <cuda_runtime.h>
#include <cuda_bf16.h>
#include <math.h>
#include <cstdint>

// Problem constants
#define B   4
#define C   256
#define H   64
#define W   64
#define O   256
#define K   9           // 3x3
#define HW  4096        // H*W
#define CK  2304        // C*K
#define KP  4608        // 2*CK (hi | lo)
#define NPIX 16384      // B*H*W

// GEMM config
#define KC      64      // K elems per chunk (bf16) = 128B rows
#define NCHUNK  108     // 3 passes x (2304/64)
#define STG     4       // cp.async pipeline stages
#define STAGE_BYTES 32768   // A 16KB + B 16KB
#define SMEM_DYN (1024 + STG * STAGE_BYTES)

// ---------------- scratch (__device__ globals; no allocs allowed) -------------
__device__ float  g_om[B * 27 * HW];
__device__ float  g_womT[256 * 9 * 28];
__device__ float4 g_spw[B * K * HW];
__device__ int4   g_spc[B * K * HW];
__device__ float  g_xhwc[(size_t)NPIX * C];         // x in NHWC
__device__ __nv_bfloat16 g_wsplit[O * KP];          // [o][hi k-major | lo k-major]
__device__ __nv_bfloat16 g_cols[(size_t)NPIX * KP]; // [px][hi k-major | lo k-major]

// ---------------- PTX helpers -------------------------------------------------
__device__ __forceinline__ uint32_t smem_u32(const void* p) {
    uint32_t a;
    asm("{ .reg .u64 t; cvta.to.shared.u64 t, %1; cvt.u32.u64 %0, t; }" : "=r"(a) : "l"(p));
    return a;
}
__device__ __forceinline__ void cp16(uint32_t dst, const void* src) {
    asm volatile("cp.async.cg.shared.global [%0], [%1], 16;" :: "r"(dst), "l"(src) : "memory");
}
#define CP_COMMIT() asm volatile("cp.async.commit_group;" ::: "memory")
#define CP_WAIT2()  asm volatile("cp.async.wait_group 2;" ::: "memory")
#define CP_WAIT0()  asm volatile("cp.async.wait_group 0;" ::: "memory")

__device__ __forceinline__ uint32_t sw128(uint32_t off) { return off ^ ((off >> 3) & 0x70); }

__device__ __forceinline__ void ldsm_x4(uint32_t* r, uint32_t addr) {
    asm volatile("ldmatrix.sync.aligned.m8n8.x4.shared.b16 {%0,%1,%2,%3}, [%4];"
        : "=r"(r[0]), "=r"(r[1]), "=r"(r[2]), "=r"(r[3]) : "r"(addr));
}
__device__ __forceinline__ void mma16816(float* d, const uint32_t* a, const uint32_t* b) {
    asm volatile("mma.sync.aligned.m16n8k16.row.col.f32.bf16.bf16.f32 "
        "{%0,%1,%2,%3}, {%4,%5,%6,%7}, {%8,%9}, {%0,%1,%2,%3};"
        : "+f"(d[0]), "+f"(d[1]), "+f"(d[2]), "+f"(d[3])
        : "r"(a[0]), "r"(a[1]), "r"(a[2]), "r"(a[3]), "r"(b[0]), "r"(b[1]));
}

// ---------------- kernel A: NCHW -> NHWC transpose ----------------------------
// grid (HW/32, C/32, B), block (32, 8)
__global__ void transpose_kernel(const float* __restrict__ x) {
    __shared__ float t[32][33];
    const int hw0 = blockIdx.x << 5;
    const int c0  = blockIdx.y << 5;
    const int b   = blockIdx.z;
    const int tx = threadIdx.x, ty = threadIdx.y;
    #pragma unroll
    for (int j = 0; j < 4; ++j) {
        int c = c0 + ty + 8 * j;
        t[ty + 8 * j][tx] = x[(((b << 8) + c) << 12) + hw0 + tx];
    }
    __syncthreads();
    #pragma unroll
    for (int j = 0; j < 4; ++j) {
        int hw = hw0 + ty + 8 * j;
        g_xhwc[(size_t)(((b << 12) + hw) << 8) + c0 + tx] = t[tx][ty + 8 * j];
    }
}

// ---------------- kernel 1: repack w_om  [oc][c][j] -> [c][j][oc pad 28] ------
__global__ void repack_wom_kernel(const float* __restrict__ w_om) {
    int d = blockIdx.x * blockDim.x + threadIdx.x;
    int c = d / 252;
    int r = d - c * 252;
    int j = r / 28;
    int oc = r - j * 28;
    float v = (oc < 27) ? w_om[oc * CK + c * 9 + j] : 0.0f;
    g_womT[d] = v;
}

// ---------------- kernel 1b: split main conv weights, K-MAJOR ordering --------
__global__ void wsplit_kernel(const float* __restrict__ weight) {
    int i = blockIdx.x * blockDim.x + threadIdx.x;   // < 256*2304
    float v = weight[i];
    __nv_bfloat16 hi = __float2bfloat16(v);
    __nv_bfloat16 lo = __float2bfloat16(v - __bfloat162float(hi));
    int o = i / CK, r = i - o * CK;
    int c = r / 9, k = r - c * 9;
    int ck = k * 256 + c;                            // k-major
    g_wsplit[o * KP + ck]      = hi;
    g_wsplit[o * KP + CK + ck] = lo;
}

// ---------------- kernel 2: offset conv v2 (27ch 3x3, pad 1) ------------------
// grid (h=64, b=4), block 256 = 4 c-segments x 64 px; smem reduce, no atomics.
__global__ void __launch_bounds__(256) offset_conv_kernel(const float* __restrict__ x) {
    __shared__ __align__(16) float xs[4][3][66];
    __shared__ __align__(16) float ws[4][252];
    __shared__ __align__(16) float red[4][28][64];   // 28 KB

    const int h  = blockIdx.x;
    const int b  = blockIdx.y;
    const int tid = threadIdx.x;
    const int cs = tid >> 6;
    const int w  = tid & 63;

    float acc[28];
    #pragma unroll
    for (int i = 0; i < 28; ++i) acc[i] = 0.0f;

    if (w < 6) xs[cs][w >> 1][(w & 1) * 65] = 0.0f;

    for (int ci = 0; ci < 64; ++ci) {
        const int c = cs * 64 + ci;
        __syncthreads();
        const float* xp = x + (((b << 8) + c) << 12);
        #pragma unroll
        for (int r = 0; r < 3; ++r) {
            int hr = h + r - 1;
            xs[cs][r][w + 1] = (hr >= 0 && hr < H) ? xp[hr * W + w] : 0.0f;
        }
        for (int i = w; i < 252; i += 64) ws[cs][i] = g_womT[c * 252 + i];
        __syncthreads();

        float xr[9];
        #pragma unroll
        for (int ky = 0; ky < 3; ++ky)
            #pragma unroll
            for (int kx = 0; kx < 3; ++kx)
                xr[ky * 3 + kx] = xs[cs][ky][w + kx];

        const float4* ws4 = reinterpret_cast<const float4*>(ws[cs]);
        #pragma unroll
        for (int j = 0; j < 9; ++j) {
            float xv = xr[j];
            #pragma unroll
            for (int q = 0; q < 7; ++q) {
                float4 wv = ws4[j * 7 + q];
                acc[q * 4 + 0] += xv * wv.x;
                acc[q * 4 + 1] += xv * wv.y;
                acc[q * 4 + 2] += xv * wv.z;
                acc[q * 4 + 3] += xv * wv.w;
            }
        }
    }

    __syncthreads();
    #pragma unroll
    for (int q = 0; q < 28; ++q) red[cs][q][w] = acc[q];
    __syncthreads();

    for (int i = tid; i < 27 * 64; i += 256) {
        int oc = i >> 6, ww = i & 63;
        float s = red[0][oc][ww] + red[1][oc][ww] + red[2][oc][ww] + red[3][oc][ww];
        g_om[(b * 27 + oc) * HW + h * W + ww] = s;
    }
}

// ---------------- kernel 3: offsets/mask -> sampling params -------------------
__global__ void params_kernel(const float* __restrict__ b_om) {
    int idx = blockIdx.x * blockDim.x + threadIdx.x;
    int b  = idx / (K * HW);
    int r  = idx - b * (K * HW);
    int k  = r >> 12;
    int hw = r & 4095;
    int h  = hw >> 6;
    int w  = hw & 63;

    const float* omb = g_om + b * 27 * HW;
    float off_y = omb[(2 * k    ) * HW + hw] + b_om[2 * k];
    float off_x = omb[(2 * k + 1) * HW + hw] + b_om[2 * k + 1];
    float mval  = omb[(18 + k   ) * HW + hw] + b_om[18 + k];
    float m = 1.0f / (1.0f + expf(-mval));

    float py = (float)(h - 1 + k / 3) + off_y;
    float px = (float)(w - 1 + k % 3) + off_x;

    float y0f = floorf(py), x0f = floorf(px);
    float ly = py - y0f, lx = px - x0f;
    int y0 = (int)y0f, x0 = (int)x0f;
    int y1 = y0 + 1,   x1 = x0 + 1;

    float vy0 = (y0 >= 0 && y0 < H) ? 1.0f : 0.0f;
    float vy1 = (y1 >= 0 && y1 < H) ? 1.0f : 0.0f;
    float vx0 = (x0 >= 0 && x0 < W) ? 1.0f : 0.0f;
    float vx1 = (x1 >= 0 && x1 < W) ? 1.0f : 0.0f;

    float4 wv;
    wv.x = (1.0f - ly) * (1.0f - lx) * m * vy0 * vx0;
    wv.y = (1.0f - ly) * lx          * m * vy0 * vx1;
    wv.z = ly * (1.0f - lx)          * m * vy1 * vx0;
    wv.w = ly * lx                   * m * vy1 * vx1;

    int4 cv;
    cv.x = min(max(y0, 0), H - 1) * W;
    cv.y = min(max(y1, 0), H - 1) * W;
    cv.z = min(max(x0, 0), W - 1);
    cv.w = min(max(x1, 0), W - 1);

    g_spw[idx] = wv;
    g_spc[idx] = cv;
}

// ---------------- kernel 4: gather v2 (channel-coalesced, k-major cols) -------
// grid 2048, block 256 = 8 warps; warp = one pixel, lane = channel.
__global__ void __launch_bounds__(256) gather_kernel() {
    const int tid  = threadIdx.x;
    const int wid  = tid >> 5;
    const int lane = tid & 31;
    const int px   = (blockIdx.x << 3) + wid;
    const int b    = px >> 12;
    const int hw   = px & 4095;

    const float* xb = g_xhwc + ((size_t)b << 20);          // b*HW*C
    __nv_bfloat16* outp = g_cols + (size_t)px * KP;

    #pragma unroll
    for (int k = 0; k < K; ++k) {
        const int gi = (b * K + k) * HW + hw;
        // broadcast loads (all lanes same address -> 1 wavefront)
        const float4 ww = g_spw[gi];
        const int4   cc = g_spc[gi];
        const int p00 = (cc.x + cc.z) << 8;
        const int p01 = (cc.x + cc.w) << 8;
        const int p10 = (cc.y + cc.z) << 8;
        const int p11 = (cc.y + cc.w) << 8;
        #pragma unroll
        for (int ch = 0; ch < 8; ++ch) {
            const int c = (ch << 5) + lane;
            float v = ww.x * xb[p00 + c] + ww.y * xb[p01 + c]
                    + ww.z * xb[p10 + c] + ww.w * xb[p11 + c];
            __nv_bfloat16 hi = __float2bfloat16(v);
            __nv_bfloat16 lo = __float2bfloat16(v - __bfloat162float(hi));
            outp[k * 256 + c]      = hi;
            outp[CK + k * 256 + c] = lo;
        }
    }
}

// ---------------- kernel 5: HMMA GEMM  D[o, px] = Wsplit x Cols^T -------------
// grid (128, 2): x = px tile (128 px), y = o tile (128 o). 256 threads (8 warps).
// warp tile 64(m) x 32(n): warps laid out 2(m) x 4(n).
__global__ void __launch_bounds__(256, 1)
gemm_kernel(const float* __restrict__ bias, float* __restrict__ out) {
    extern __shared__ __align__(16) char dyn_smem[];
    const uint32_t smem_base = smem_u32(dyn_smem);
    const uint32_t tile0 = (smem_base + 1023u) & ~1023u;   // 1024-aligned stages

    const int tid  = threadIdx.x;
    const int wid  = tid >> 5;
    const int lane = tid & 31;
    const int o_tile = blockIdx.y;            // 0..1
    const int pxb    = blockIdx.x << 7;       // 128 px per CTA

    const int wm = wid & 1;                   // 0..1  -> m offset 64*wm
    const int wn = wid >> 1;                  // 0..3  -> n offset 32*wn

    const __nv_bfloat16* wA = g_wsplit + (size_t)o_tile * 128 * KP;
    const __nv_bfloat16* cB = g_cols + (size_t)pxb * KP;

    const int rL = tid >> 1;                 // 0..127
    const int sL = (tid & 1) << 1;           // seg 0/2 base, +1 below

    auto load_chunk = [&](int j) {
        int st = j % STG;
        uint32_t sa = tile0 + st * STAGE_BYTES;
        uint32_t sb = sa + 16384;
        int p  = j / 36;
        int kc = (j - p * 36) * KC;
        int aoff = ((p == 2) ? CK : 0) + kc;
        int boff = ((p == 1) ? CK : 0) + kc;
        const __nv_bfloat16* wr = wA + (size_t)rL * KP + aoff;
        const __nv_bfloat16* cr = cB + (size_t)rL * KP + boff;
        #pragma unroll
        for (int q = 0; q < 2; ++q) {
            int sg = sL + q;
            cp16(sa + sw128((uint32_t)(rL * 128 + sg * 16)), wr + sg * 8);
            cp16(sb + sw128((uint32_t)(rL * 128 + sg * 16)), cr + sg * 8);
        }
        #pragma unroll
        for (int q = 0; q < 2; ++q) {
            int sg = sL + q + 4;
            cp16(sa + sw128((uint32_t)(rL * 128 + sg * 16)), wr + sg * 8);
            cp16(sb + sw128((uint32_t)(rL * 128 + sg * 16)), cr + sg * 8);
        }
        CP_COMMIT();
    };

    float acc[4][4][4];
    #pragma unroll
    for (int i = 0; i < 4; ++i)
        #pragma unroll
        for (int j = 0; j < 4; ++j)
            #pragma unroll
            for (int q = 0; q < 4; ++q) acc[i][j][q] = 0.0f;

    const uint32_t aRow = (uint32_t)(wm * 64 + (lane & 15));
    const uint32_t aCb  = (uint32_t)((lane >> 4) << 4);
    const uint32_t bRow = (uint32_t)(wn * 32 + ((lane >> 4) << 3) + (lane & 7));
    const uint32_t bCb  = (uint32_t)(((lane >> 3) & 1) << 4);

    load_chunk(0);
    load_chunk(1);
    load_chunk(2);

    for (int i = 0; i < NCHUNK; ++i) {
        CP_WAIT2();
        __syncthreads();
        if (i + STG - 1 < NCHUNK) load_chunk(i + STG - 1);

        int st = i % STG;
        uint32_t sa = tile0 + st * STAGE_BYTES;
        uint32_t sb = sa + 16384;

        #pragma unroll
        for (int kk = 0; kk < 4; ++kk) {
            uint32_t a[4][4], b[4][2];
            #pragma unroll
            for (int mf = 0; mf < 4; ++mf)
                ldsm_x4(a[mf], sa + sw128((aRow + mf * 16) * 128 + aCb + kk * 32));
            #pragma unroll
            for (int half = 0; half < 2; ++half) {
                uint32_t r[4];
                ldsm_x4(r, sb + sw128((bRow + half * 16) * 128 + bCb + kk * 32));
                b[2 * half][0] = r[0]; b[2 * half][1] = r[1];
                b[2 * half + 1][0] = r[2]; b[2 * half + 1][1] = r[3];
            }
            #pragma unroll
            for (int mf = 0; mf < 4; ++mf)
                #pragma unroll
                for (int nf = 0; nf < 4; ++nf)
                    mma16816(acc[mf][nf], a[mf], b[nf]);
        }
    }
    CP_WAIT0();

    // ---- epilogue: direct register -> gmem stores -----------------------------
    const int bb  = pxb >> 12;
    const int hw0 = pxb & 4095;
    const int oBase = o_tile * 128 + wm * 64 + (lane >> 2);
    const int nBase = hw0 + wn * 32 + (lane & 3) * 2;

    #pragma unroll
    for (int mf = 0; mf < 4; ++mf) {
        int o0 = oBase + mf * 16;
        float bz0 = __ldg(bias + o0);
        float bz8 = __ldg(bias + o0 + 8);
        float* op0 = out + (bb << 20) + (o0 << 12) + nBase;
        float* op8 = op0 + (8 << 12);
        #pragma unroll
        for (int nf = 0; nf < 4; ++nf) {
            float2 v0 = make_float2(acc[mf][nf][0] + bz0, acc[mf][nf][1] + bz0);
            float2 v1 = make_float2(acc[mf][nf][2] + bz8, acc[mf][nf][3] + bz8);
            *reinterpret_cast<float2*>(op0 + nf * 8) = v0;
            *reinterpret_cast<float2*>(op8 + nf * 8) = v1;
        }
    }
}

// ---------------- launch ------------------------------------------------------
extern "C" void kernel_launch(void* const* d_in, const int* in_sizes, int n_in,
                              void* d_out, int out_size) {
    const float* x      = (const float*)d_in[0];   // (4,256,64,64)
    const float* w_om   = (const float*)d_in[1];   // (27,256,3,3)
    const float* b_om   = (const float*)d_in[2];   // (27,)
    const float* weight = (const float*)d_in[3];   // (256,256,3,3)
    const float* bias   = (const float*)d_in[4];   // (256,)
    float* out = (float*)d_out;                    // (4,256,64,64)

    cudaFuncSetAttribute(gemm_kernel, cudaFuncAttributeMaxDynamicSharedMemorySize, SMEM_DYN);

    transpose_kernel<<<dim3(128, 8, 4), dim3(32, 8)>>>(x);
    repack_wom_kernel<<<63, 1024>>>(w_om);
    wsplit_kernel<<<576, 1024>>>(weight);
    offset_conv_kernel<<<dim3(64, 4), 256>>>(x);
    params_kernel<<<144, 1024>>>(b_om);
    gather_kernel<<<2048, 256>>>();
    gemm_kernel<<<dim3(128, 2), 256, SMEM_DYN>>>(bias, out);
}

// round 6
// speedup vs baseline: 3.1768x; 1.2209x over previous
#include <cuda_runtime.h>
#include <cuda_bf16.h>
#include <math.h>
#include <cstdint>

// Problem constants
#define B   4
#define C   256
#define H   64
#define W   64
#define O   256
#define K   9           // 3x3
#define HW  4096        // H*W
#define CK  2304        // C*K
#define KP  4608        // 2*CK (hi | lo)
#define NPIX 16384      // B*H*W

// GEMM config
#define KC      64      // K elems per chunk (bf16) = 128B rows
#define NCHUNK  108     // 3 passes x (2304/64)
#define STG     4       // cp.async pipeline stages
#define STAGE_BYTES 32768   // A 16KB + B 16KB
#define SMEM_DYN (1024 + STG * STAGE_BYTES)

#define NSEG 8                       // channel segments in offset conv
#define SEG_STRIDE (B * 27 * HW)     // per-segment partial block

// ---------------- scratch (__device__ globals; no allocs allowed) -------------
__device__ float  g_part[NSEG * SEG_STRIDE];        // offset-conv partials
__device__ float  g_womT[256 * 9 * 28];
__device__ float4 g_spw[B * K * HW];
__device__ int4   g_spc[B * K * HW];
__device__ float  g_xhwc[(size_t)NPIX * C];         // x in NHWC
__device__ __nv_bfloat16 g_wsplit[O * KP];          // [o][hi k-major | lo k-major]
__device__ __nv_bfloat16 g_cols[(size_t)NPIX * KP]; // [px][hi k-major | lo k-major]

// ---------------- PTX helpers -------------------------------------------------
__device__ __forceinline__ uint32_t smem_u32(const void* p) {
    uint32_t a;
    asm("{ .reg .u64 t; cvta.to.shared.u64 t, %1; cvt.u32.u64 %0, t; }" : "=r"(a) : "l"(p));
    return a;
}
__device__ __forceinline__ void cp16(uint32_t dst, const void* src) {
    asm volatile("cp.async.cg.shared.global [%0], [%1], 16;" :: "r"(dst), "l"(src) : "memory");
}
#define CP_COMMIT() asm volatile("cp.async.commit_group;" ::: "memory")
#define CP_WAIT2()  asm volatile("cp.async.wait_group 2;" ::: "memory")
#define CP_WAIT0()  asm volatile("cp.async.wait_group 0;" ::: "memory")

__device__ __forceinline__ uint32_t sw128(uint32_t off) { return off ^ ((off >> 3) & 0x70); }

__device__ __forceinline__ void ldsm_x4(uint32_t* r, uint32_t addr) {
    asm volatile("ldmatrix.sync.aligned.m8n8.x4.shared.b16 {%0,%1,%2,%3}, [%4];"
        : "=r"(r[0]), "=r"(r[1]), "=r"(r[2]), "=r"(r[3]) : "r"(addr));
}
__device__ __forceinline__ void mma16816(float* d, const uint32_t* a, const uint32_t* b) {
    asm volatile("mma.sync.aligned.m16n8k16.row.col.f32.bf16.bf16.f32 "
        "{%0,%1,%2,%3}, {%4,%5,%6,%7}, {%8,%9}, {%0,%1,%2,%3};"
        : "+f"(d[0]), "+f"(d[1]), "+f"(d[2]), "+f"(d[3])
        : "r"(a[0]), "r"(a[1]), "r"(a[2]), "r"(a[3]), "r"(b[0]), "r"(b[1]));
}

// ---------------- kernel A: NCHW -> NHWC transpose ----------------------------
// grid (HW/32, C/32, B), block (32, 8)
__global__ void transpose_kernel(const float* __restrict__ x) {
    __shared__ float t[32][33];
    const int hw0 = blockIdx.x << 5;
    const int c0  = blockIdx.y << 5;
    const int b   = blockIdx.z;
    const int tx = threadIdx.x, ty = threadIdx.y;
    #pragma unroll
    for (int j = 0; j < 4; ++j) {
        int c = c0 + ty + 8 * j;
        t[ty + 8 * j][tx] = x[(((b << 8) + c) << 12) + hw0 + tx];
    }
    __syncthreads();
    #pragma unroll
    for (int j = 0; j < 4; ++j) {
        int hw = hw0 + ty + 8 * j;
        g_xhwc[(size_t)(((b << 12) + hw) << 8) + c0 + tx] = t[tx][ty + 8 * j];
    }
}

// ---------------- kernel 1: repack w_om  [oc][c][j] -> [c][j][oc pad 28] ------
__global__ void repack_wom_kernel(const float* __restrict__ w_om) {
    int d = blockIdx.x * blockDim.x + threadIdx.x;
    int c = d / 252;
    int r = d - c * 252;
    int j = r / 28;
    int oc = r - j * 28;
    float v = (oc < 27) ? w_om[oc * CK + c * 9 + j] : 0.0f;
    g_womT[d] = v;
}

// ---------------- kernel 1b: split main conv weights, K-MAJOR ordering --------
__global__ void wsplit_kernel(const float* __restrict__ weight) {
    int i = blockIdx.x * blockDim.x + threadIdx.x;   // < 256*2304
    float v = weight[i];
    __nv_bfloat16 hi = __float2bfloat16(v);
    __nv_bfloat16 lo = __float2bfloat16(v - __bfloat162float(hi));
    int o = i / CK, r = i - o * CK;
    int c = r / 9, k = r - c * 9;
    int ck = k * 256 + c;                            // k-major
    g_wsplit[o * KP + ck]      = hi;
    g_wsplit[o * KP + CK + ck] = lo;
}

// ---------------- kernel 2: offset conv v3 (warp-autonomous, no atomics) ------
// grid (hgrp=8, b=4, cs=8), block 256 = 8 warps; warp = one h row of one c-seg.
// Lane covers pixels w = 2*lane, 2*lane+1. Partials to g_part[cs].
__global__ void __launch_bounds__(256) offset_conv_kernel(const float* __restrict__ x) {
    __shared__ __align__(16) float ws[8064];         // 32 ch x 252

    const int tid = threadIdx.x;
    const int wid = tid >> 5;
    const int lane = tid & 31;
    const int h  = (blockIdx.x << 3) + wid;
    const int b  = blockIdx.y;
    const int cs = blockIdx.z;
    const int c0 = cs << 5;

    // stage this segment's repacked weights once (coalesced), single barrier
    for (int i = tid; i < 8064; i += 256) ws[i] = g_womT[c0 * 252 + i];
    __syncthreads();

    float acc_e[28], acc_o[28];
    #pragma unroll
    for (int i = 0; i < 28; ++i) { acc_e[i] = 0.0f; acc_o[i] = 0.0f; }

    const unsigned FULL = 0xFFFFFFFFu;

    for (int ci = 0; ci < 32; ++ci) {
        const int c = c0 + ci;
        const float* xp = x + (((b << 8) + c) << 12) + (h << 6) + (lane << 1);

        float2 r0 = (h > 0)      ? *reinterpret_cast<const float2*>(xp - 64) : make_float2(0.f, 0.f);
        float2 r1 =                *reinterpret_cast<const float2*>(xp);
        float2 r2 = (h < H - 1)  ? *reinterpret_cast<const float2*>(xp + 64) : make_float2(0.f, 0.f);

        float le0 = __shfl_up_sync(FULL, r0.y, 1); if (lane == 0) le0 = 0.f;
        float le1 = __shfl_up_sync(FULL, r1.y, 1); if (lane == 0) le1 = 0.f;
        float le2 = __shfl_up_sync(FULL, r2.y, 1); if (lane == 0) le2 = 0.f;
        float ri0 = __shfl_down_sync(FULL, r0.x, 1); if (lane == 31) ri0 = 0.f;
        float ri1 = __shfl_down_sync(FULL, r1.x, 1); if (lane == 31) ri1 = 0.f;
        float ri2 = __shfl_down_sync(FULL, r2.x, 1); if (lane == 31) ri2 = 0.f;

        // taps for even pixel (w=2l): [left, x, y]; odd pixel (w=2l+1): [x, y, right]
        float xe[9], xo[9];
        xe[0] = le0;  xo[0] = r0.x;
        xe[1] = r0.x; xo[1] = r0.y;
        xe[2] = r0.y; xo[2] = ri0;
        xe[3] = le1;  xo[3] = r1.x;
        xe[4] = r1.x; xo[4] = r1.y;
        xe[5] = r1.y; xo[5] = ri1;
        xe[6] = le2;  xo[6] = r2.x;
        xe[7] = r2.x; xo[7] = r2.y;
        xe[8] = r2.y; xo[8] = ri2;

        const float4* w4 = reinterpret_cast<const float4*>(ws + ci * 252);
        #pragma unroll
        for (int j = 0; j < 9; ++j) {
            float ve = xe[j], vo = xo[j];
            #pragma unroll
            for (int q = 0; q < 7; ++q) {
                float4 wv = w4[j * 7 + q];   // broadcast LDS.128
                acc_e[q * 4 + 0] = fmaf(ve, wv.x, acc_e[q * 4 + 0]);
                acc_o[q * 4 + 0] = fmaf(vo, wv.x, acc_o[q * 4 + 0]);
                acc_e[q * 4 + 1] = fmaf(ve, wv.y, acc_e[q * 4 + 1]);
                acc_o[q * 4 + 1] = fmaf(vo, wv.y, acc_o[q * 4 + 1]);
                acc_e[q * 4 + 2] = fmaf(ve, wv.z, acc_e[q * 4 + 2]);
                acc_o[q * 4 + 2] = fmaf(vo, wv.z, acc_o[q * 4 + 2]);
                acc_e[q * 4 + 3] = fmaf(ve, wv.w, acc_e[q * 4 + 3]);
                acc_o[q * 4 + 3] = fmaf(vo, wv.w, acc_o[q * 4 + 3]);
            }
        }
    }

    float* pp = g_part + cs * SEG_STRIDE + (b * 27) * HW + (h << 6) + (lane << 1);
    #pragma unroll
    for (int oc = 0; oc < 27; ++oc)
        *reinterpret_cast<float2*>(pp + oc * HW) = make_float2(acc_e[oc], acc_o[oc]);
}

// ---------------- kernel 3: offsets/mask -> sampling params -------------------
__device__ __forceinline__ float sum_part(int off) {
    float s = 0.0f;
    #pragma unroll
    for (int cs = 0; cs < NSEG; ++cs) s += g_part[cs * SEG_STRIDE + off];
    return s;
}

__global__ void params_kernel(const float* __restrict__ b_om) {
    int idx = blockIdx.x * blockDim.x + threadIdx.x;
    int b  = idx / (K * HW);
    int r  = idx - b * (K * HW);
    int k  = r >> 12;
    int hw = r & 4095;
    int h  = hw >> 6;
    int w  = hw & 63;

    const int base = b * 27 * HW + hw;
    float off_y = sum_part(base + (2 * k    ) * HW) + b_om[2 * k];
    float off_x = sum_part(base + (2 * k + 1) * HW) + b_om[2 * k + 1];
    float mval  = sum_part(base + (18 + k   ) * HW) + b_om[18 + k];
    float m = 1.0f / (1.0f + expf(-mval));

    float py = (float)(h - 1 + k / 3) + off_y;
    float px = (float)(w - 1 + k % 3) + off_x;

    float y0f = floorf(py), x0f = floorf(px);
    float ly = py - y0f, lx = px - x0f;
    int y0 = (int)y0f, x0 = (int)x0f;
    int y1 = y0 + 1,   x1 = x0 + 1;

    float vy0 = (y0 >= 0 && y0 < H) ? 1.0f : 0.0f;
    float vy1 = (y1 >= 0 && y1 < H) ? 1.0f : 0.0f;
    float vx0 = (x0 >= 0 && x0 < W) ? 1.0f : 0.0f;
    float vx1 = (x1 >= 0 && x1 < W) ? 1.0f : 0.0f;

    float4 wv;
    wv.x = (1.0f - ly) * (1.0f - lx) * m * vy0 * vx0;
    wv.y = (1.0f - ly) * lx          * m * vy0 * vx1;
    wv.z = ly * (1.0f - lx)          * m * vy1 * vx0;
    wv.w = ly * lx                   * m * vy1 * vx1;

    int4 cv;
    cv.x = min(max(y0, 0), H - 1) * W;
    cv.y = min(max(y1, 0), H - 1) * W;
    cv.z = min(max(x0, 0), W - 1);
    cv.w = min(max(x1, 0), W - 1);

    g_spw[idx] = wv;
    g_spc[idx] = cv;
}

// ---------------- kernel 4: gather v2 (channel-coalesced, k-major cols) -------
// grid 2048, block 256 = 8 warps; warp = one pixel, lane = channel.
__global__ void __launch_bounds__(256) gather_kernel() {
    const int tid  = threadIdx.x;
    const int wid  = tid >> 5;
    const int lane = tid & 31;
    const int px   = (blockIdx.x << 3) + wid;
    const int b    = px >> 12;
    const int hw   = px & 4095;

    const float* xb = g_xhwc + ((size_t)b << 20);          // b*HW*C
    __nv_bfloat16* outp = g_cols + (size_t)px * KP;

    #pragma unroll
    for (int k = 0; k < K; ++k) {
        const int gi = (b * K + k) * HW + hw;
        const float4 ww = g_spw[gi];
        const int4   cc = g_spc[gi];
        const int p00 = (cc.x + cc.z) << 8;
        const int p01 = (cc.x + cc.w) << 8;
        const int p10 = (cc.y + cc.z) << 8;
        const int p11 = (cc.y + cc.w) << 8;
        #pragma unroll
        for (int ch = 0; ch < 8; ++ch) {
            const int c = (ch << 5) + lane;
            float v = ww.x * xb[p00 + c] + ww.y * xb[p01 + c]
                    + ww.z * xb[p10 + c] + ww.w * xb[p11 + c];
            __nv_bfloat16 hi = __float2bfloat16(v);
            __nv_bfloat16 lo = __float2bfloat16(v - __bfloat162float(hi));
            outp[k * 256 + c]      = hi;
            outp[CK + k * 256 + c] = lo;
        }
    }
}

// ---------------- kernel 5: HMMA GEMM  D[o, px] = Wsplit x Cols^T -------------
// grid (128, 2): x = px tile (128 px), y = o tile (128 o). 256 threads (8 warps).
// warp tile 64(m) x 32(n): warps laid out 2(m) x 4(n).
__global__ void __launch_bounds__(256, 1)
gemm_kernel(const float* __restrict__ bias, float* __restrict__ out) {
    extern __shared__ __align__(16) char dyn_smem[];
    const uint32_t smem_base = smem_u32(dyn_smem);
    const uint32_t tile0 = (smem_base + 1023u) & ~1023u;   // 1024-aligned stages

    const int tid  = threadIdx.x;
    const int wid  = tid >> 5;
    const int lane = tid & 31;
    const int o_tile = blockIdx.y;            // 0..1
    const int pxb    = blockIdx.x << 7;       // 128 px per CTA

    const int wm = wid & 1;                   // 0..1  -> m offset 64*wm
    const int wn = wid >> 1;                  // 0..3  -> n offset 32*wn

    const __nv_bfloat16* wA = g_wsplit + (size_t)o_tile * 128 * KP;
    const __nv_bfloat16* cB = g_cols + (size_t)pxb * KP;

    const int rL = tid >> 1;                 // 0..127
    const int sL = (tid & 1) << 1;           // seg 0/2 base, +1 below

    auto load_chunk = [&](int j) {
        int st = j % STG;
        uint32_t sa = tile0 + st * STAGE_BYTES;
        uint32_t sb = sa + 16384;
        int p  = j / 36;
        int kc = (j - p * 36) * KC;
        int aoff = ((p == 2) ? CK : 0) + kc;
        int boff = ((p == 1) ? CK : 0) + kc;
        const __nv_bfloat16* wr = wA + (size_t)rL * KP + aoff;
        const __nv_bfloat16* cr = cB + (size_t)rL * KP + boff;
        #pragma unroll
        for (int q = 0; q < 2; ++q) {
            int sg = sL + q;
            cp16(sa + sw128((uint32_t)(rL * 128 + sg * 16)), wr + sg * 8);
            cp16(sb + sw128((uint32_t)(rL * 128 + sg * 16)), cr + sg * 8);
        }
        #pragma unroll
        for (int q = 0; q < 2; ++q) {
            int sg = sL + q + 4;
            cp16(sa + sw128((uint32_t)(rL * 128 + sg * 16)), wr + sg * 8);
            cp16(sb + sw128((uint32_t)(rL * 128 + sg * 16)), cr + sg * 8);
        }
        CP_COMMIT();
    };

    float acc[4][4][4];
    #pragma unroll
    for (int i = 0; i < 4; ++i)
        #pragma unroll
        for (int j = 0; j < 4; ++j)
            #pragma unroll
            for (int q = 0; q < 4; ++q) acc[i][j][q] = 0.0f;

    const uint32_t aRow = (uint32_t)(wm * 64 + (lane & 15));
    const uint32_t aCb  = (uint32_t)((lane >> 4) << 4);
    const uint32_t bRow = (uint32_t)(wn * 32 + ((lane >> 4) << 3) + (lane & 7));
    const uint32_t bCb  = (uint32_t)(((lane >> 3) & 1) << 4);

    load_chunk(0);
    load_chunk(1);
    load_chunk(2);

    for (int i = 0; i < NCHUNK; ++i) {
        CP_WAIT2();
        __syncthreads();
        if (i + STG - 1 < NCHUNK) load_chunk(i + STG - 1);

        int st = i % STG;
        uint32_t sa = tile0 + st * STAGE_BYTES;
        uint32_t sb = sa + 16384;

        #pragma unroll
        for (int kk = 0; kk < 4; ++kk) {
            uint32_t a[4][4], b[4][2];
            #pragma unroll
            for (int mf = 0; mf < 4; ++mf)
                ldsm_x4(a[mf], sa + sw128((aRow + mf * 16) * 128 + aCb + kk * 32));
            #pragma unroll
            for (int half = 0; half < 2; ++half) {
                uint32_t r[4];
                ldsm_x4(r, sb + sw128((bRow + half * 16) * 128 + bCb + kk * 32));
                b[2 * half][0] = r[0]; b[2 * half][1] = r[1];
                b[2 * half + 1][0] = r[2]; b[2 * half + 1][1] = r[3];
            }
            #pragma unroll
            for (int mf = 0; mf < 4; ++mf)
                #pragma unroll
                for (int nf = 0; nf < 4; ++nf)
                    mma16816(acc[mf][nf], a[mf], b[nf]);
        }
    }
    CP_WAIT0();

    // ---- epilogue: direct register -> gmem stores -----------------------------
    const int bb  = pxb >> 12;
    const int hw0 = pxb & 4095;
    const int oBase = o_tile * 128 + wm * 64 + (lane >> 2);
    const int nBase = hw0 + wn * 32 + (lane & 3) * 2;

    #pragma unroll
    for (int mf = 0; mf < 4; ++mf) {
        int o0 = oBase + mf * 16;
        float bz0 = __ldg(bias + o0);
        float bz8 = __ldg(bias + o0 + 8);
        float* op0 = out + (bb << 20) + (o0 << 12) + nBase;
        float* op8 = op0 + (8 << 12);
        #pragma unroll
        for (int nf = 0; nf < 4; ++nf) {
            float2 v0 = make_float2(acc[mf][nf][0] + bz0, acc[mf][nf][1] + bz0);
            float2 v1 = make_float2(acc[mf][nf][2] + bz8, acc[mf][nf][3] + bz8);
            *reinterpret_cast<float2*>(op0 + nf * 8) = v0;
            *reinterpret_cast<float2*>(op8 + nf * 8) = v1;
        }
    }
}

// ---------------- launch ------------------------------------------------------
extern "C" void kernel_launch(void* const* d_in, const int* in_sizes, int n_in,
                              void* d_out, int out_size) {
    const float* x      = (const float*)d_in[0];   // (4,256,64,64)
    const float* w_om   = (const float*)d_in[1];   // (27,256,3,3)
    const float* b_om   = (const float*)d_in[2];   // (27,)
    const float* weight = (const float*)d_in[3];   // (256,256,3,3)
    const float* bias   = (const float*)d_in[4];   // (256,)
    float* out = (float*)d_out;                    // (4,256,64,64)

    cudaFuncSetAttribute(gemm_kernel, cudaFuncAttributeMaxDynamicSharedMemorySize, SMEM_DYN);

    transpose_kernel<<<dim3(128, 8, 4), dim3(32, 8)>>>(x);
    repack_wom_kernel<<<63, 1024>>>(w_om);
    wsplit_kernel<<<576, 1024>>>(weight);
    offset_conv_kernel<<<dim3(8, 4, 8), 256>>>(x);
    params_kernel<<<144, 1024>>>(b_om);
    gather_kernel<<<2048, 256>>>();
    gemm_kernel<<<dim3(128, 2), 256, SMEM_DYN>>>(bias, out);
}

// round 8
// speedup vs baseline: 4.4862x; 1.4121x over previous
#include <cuda_runtime.h>
#include <cuda_bf16.h>
#include <math.h>
#include <cstdint>

// Problem constants
#define B   4
#define C   256
#define H   64
#define W   64
#define O   256
#define K   9           // 3x3
#define HW  4096        // H*W
#define CK  2304        // C*K
#define KP  4608        // 2*CK (hi | lo)
#define NPIX 16384      // B*H*W

// GEMM config
#define KC      64      // K elems per chunk (bf16) = 128B rows
#define NCHUNK  108     // 3 passes x (2304/64)
#define STG     4       // cp.async pipeline stages
#define STAGE_BYTES 49152   // A 16KB + B 32KB
#define SMEM_DYN (1024 + STG * STAGE_BYTES)

#define NSEG 8                       // channel segments in offset conv
#define SEG_STRIDE (B * 27 * HW)     // per-segment partial block

// ---------------- scratch (__device__ globals; no allocs allowed) -------------
__device__ float  g_part[NSEG * SEG_STRIDE];        // offset-conv partials
__device__ float  g_womT[256 * 9 * 28];
__device__ float4 g_spw[B * K * HW];
__device__ int4   g_spc[B * K * HW];
__device__ float  g_xhwc[(size_t)NPIX * C];         // x in NHWC
__device__ __nv_bfloat16 g_wsplit[O * KP];          // [o][hi k-major | lo k-major]
__device__ __nv_bfloat16 g_cols[(size_t)NPIX * KP]; // [px][hi k-major | lo k-major]

// ---------------- PTX helpers -------------------------------------------------
__device__ __forceinline__ uint32_t smem_u32(const void* p) {
    uint32_t a;
    asm("{ .reg .u64 t; cvta.to.shared.u64 t, %1; cvt.u32.u64 %0, t; }" : "=r"(a) : "l"(p));
    return a;
}
__device__ __forceinline__ void cp16(uint32_t dst, const void* src) {
    asm volatile("cp.async.cg.shared.global [%0], [%1], 16;" :: "r"(dst), "l"(src) : "memory");
}
#define CP_COMMIT() asm volatile("cp.async.commit_group;" ::: "memory")
#define CP_WAIT2()  asm volatile("cp.async.wait_group 2;" ::: "memory")
#define CP_WAIT0()  asm volatile("cp.async.wait_group 0;" ::: "memory")

__device__ __forceinline__ uint32_t sw128(uint32_t off) { return off ^ ((off >> 3) & 0x70); }

__device__ __forceinline__ void ldsm_x4(uint32_t* r, uint32_t addr) {
    asm volatile("ldmatrix.sync.aligned.m8n8.x4.shared.b16 {%0,%1,%2,%3}, [%4];"
        : "=r"(r[0]), "=r"(r[1]), "=r"(r[2]), "=r"(r[3]) : "r"(addr));
}
__device__ __forceinline__ void mma16816(float* d, const uint32_t* a, const uint32_t* b) {
    asm volatile("mma.sync.aligned.m16n8k16.row.col.f32.bf16.bf16.f32 "
        "{%0,%1,%2,%3}, {%4,%5,%6,%7}, {%8,%9}, {%0,%1,%2,%3};"
        : "+f"(d[0]), "+f"(d[1]), "+f"(d[2]), "+f"(d[3])
        : "r"(a[0]), "r"(a[1]), "r"(a[2]), "r"(a[3]), "r"(b[0]), "r"(b[1]));
}

// ---------------- kernel 1: fused prep (transpose + repack + wsplit) ----------
// grid 4924 x 256 threads:
//   [0, 4096)    : NCHW->NHWC transpose, block = (32px x 32ch) tile
//   [4096, 4348) : repack w_om (252 blocks x 256 = 64512 elements, exact)
//   [4348, 4924) : wsplit (576 blocks x 256 threads x 4 elems)
__global__ void __launch_bounds__(256) prep_kernel(const float* __restrict__ x,
                                                   const float* __restrict__ w_om,
                                                   const float* __restrict__ weight) {
    const int bid = blockIdx.x;
    const int tid = threadIdx.x;

    if (bid < 4096) {
        __shared__ float t[32][33];
        const int hw0 = (bid & 127) << 5;
        const int c0  = ((bid >> 7) & 7) << 5;
        const int b   = bid >> 10;
        const int tx = tid & 31, ty = tid >> 5;
        #pragma unroll
        for (int j = 0; j < 4; ++j) {
            int c = c0 + ty + 8 * j;
            t[ty + 8 * j][tx] = x[(((b << 8) + c) << 12) + hw0 + tx];
        }
        __syncthreads();
        #pragma unroll
        for (int j = 0; j < 4; ++j) {
            int hw = hw0 + ty + 8 * j;
            g_xhwc[(size_t)(((b << 12) + hw) << 8) + c0 + tx] = t[tx][ty + 8 * j];
        }
    } else if (bid < 4348) {
        int d = (bid - 4096) * 256 + tid;     // < 64512 exactly
        int c = d / 252;
        int r = d - c * 252;
        int j = r / 28;
        int oc = r - j * 28;
        g_womT[d] = (oc < 27) ? w_om[oc * CK + c * 9 + j] : 0.0f;
    } else {
        int i = (bid - 4348) * 1024 + tid * 4;  // < 589824, 4 elems per thread
        const float4 v4 = *reinterpret_cast<const float4*>(weight + i);
        const float vs[4] = { v4.x, v4.y, v4.z, v4.w };
        #pragma unroll
        for (int q = 0; q < 4; ++q) {
            float v = vs[q];
            __nv_bfloat16 hi = __float2bfloat16(v);
            __nv_bfloat16 lo = __float2bfloat16(v - __bfloat162float(hi));
            int e = i + q;
            int o = e / CK, r = e - o * CK;
            int c = r / 9, k = r - c * 9;
            int ck = k * 256 + c;                // k-major
            g_wsplit[o * KP + ck]      = hi;
            g_wsplit[o * KP + CK + ck] = lo;
        }
    }
}

// ---------------- kernel 2: offset conv v3 (warp-autonomous, no atomics) ------
// grid (hgrp=8, b=4, cs=8), block 256 = 8 warps; warp = one h row of one c-seg.
__global__ void __launch_bounds__(256) offset_conv_kernel(const float* __restrict__ x) {
    __shared__ __align__(16) float ws[8064];         // 32 ch x 252

    const int tid = threadIdx.x;
    const int wid = tid >> 5;
    const int lane = tid & 31;
    const int h  = (blockIdx.x << 3) + wid;
    const int b  = blockIdx.y;
    const int cs = blockIdx.z;
    const int c0 = cs << 5;

    for (int i = tid; i < 8064; i += 256) ws[i] = g_womT[c0 * 252 + i];
    __syncthreads();

    float acc_e[28], acc_o[28];
    #pragma unroll
    for (int i = 0; i < 28; ++i) { acc_e[i] = 0.0f; acc_o[i] = 0.0f; }

    const unsigned FULL = 0xFFFFFFFFu;

    for (int ci = 0; ci < 32; ++ci) {
        const int c = c0 + ci;
        const float* xp = x + (((b << 8) + c) << 12) + (h << 6) + (lane << 1);

        float2 r0 = (h > 0)      ? *reinterpret_cast<const float2*>(xp - 64) : make_float2(0.f, 0.f);
        float2 r1 =                *reinterpret_cast<const float2*>(xp);
        float2 r2 = (h < H - 1)  ? *reinterpret_cast<const float2*>(xp + 64) : make_float2(0.f, 0.f);

        float le0 = __shfl_up_sync(FULL, r0.y, 1); if (lane == 0) le0 = 0.f;
        float le1 = __shfl_up_sync(FULL, r1.y, 1); if (lane == 0) le1 = 0.f;
        float le2 = __shfl_up_sync(FULL, r2.y, 1); if (lane == 0) le2 = 0.f;
        float ri0 = __shfl_down_sync(FULL, r0.x, 1); if (lane == 31) ri0 = 0.f;
        float ri1 = __shfl_down_sync(FULL, r1.x, 1); if (lane == 31) ri1 = 0.f;
        float ri2 = __shfl_down_sync(FULL, r2.x, 1); if (lane == 31) ri2 = 0.f;

        float xe[9], xo[9];
        xe[0] = le0;  xo[0] = r0.x;
        xe[1] = r0.x; xo[1] = r0.y;
        xe[2] = r0.y; xo[2] = ri0;
        xe[3] = le1;  xo[3] = r1.x;
        xe[4] = r1.x; xo[4] = r1.y;
        xe[5] = r1.y; xo[5] = ri1;
        xe[6] = le2;  xo[6] = r2.x;
        xe[7] = r2.x; xo[7] = r2.y;
        xe[8] = r2.y; xo[8] = ri2;

        const float4* w4 = reinterpret_cast<const float4*>(ws + ci * 252);
        #pragma unroll
        for (int j = 0; j < 9; ++j) {
            float ve = xe[j], vo = xo[j];
            #pragma unroll
            for (int q = 0; q < 7; ++q) {
                float4 wv = w4[j * 7 + q];   // broadcast LDS.128
                acc_e[q * 4 + 0] = fmaf(ve, wv.x, acc_e[q * 4 + 0]);
                acc_o[q * 4 + 0] = fmaf(vo, wv.x, acc_o[q * 4 + 0]);
                acc_e[q * 4 + 1] = fmaf(ve, wv.y, acc_e[q * 4 + 1]);
                acc_o[q * 4 + 1] = fmaf(vo, wv.y, acc_o[q * 4 + 1]);
                acc_e[q * 4 + 2] = fmaf(ve, wv.z, acc_e[q * 4 + 2]);
                acc_o[q * 4 + 2] = fmaf(vo, wv.z, acc_o[q * 4 + 2]);
                acc_e[q * 4 + 3] = fmaf(ve, wv.w, acc_e[q * 4 + 3]);
                acc_o[q * 4 + 3] = fmaf(vo, wv.w, acc_o[q * 4 + 3]);
            }
        }
    }

    float* pp = g_part + cs * SEG_STRIDE + (b * 27) * HW + (h << 6) + (lane << 1);
    #pragma unroll
    for (int oc = 0; oc < 27; ++oc)
        *reinterpret_cast<float2*>(pp + oc * HW) = make_float2(acc_e[oc], acc_o[oc]);
}

// ---------------- kernel 3: offsets/mask -> sampling params -------------------
__device__ __forceinline__ float sum_part(int off) {
    float s = 0.0f;
    #pragma unroll
    for (int cs = 0; cs < NSEG; ++cs) s += g_part[cs * SEG_STRIDE + off];
    return s;
}

__global__ void params_kernel(const float* __restrict__ b_om) {
    int idx = blockIdx.x * blockDim.x + threadIdx.x;
    int b  = idx / (K * HW);
    int r  = idx - b * (K * HW);
    int k  = r >> 12;
    int hw = r & 4095;
    int h  = hw >> 6;
    int w  = hw & 63;

    const int base = b * 27 * HW + hw;
    float off_y = sum_part(base + (2 * k    ) * HW) + b_om[2 * k];
    float off_x = sum_part(base + (2 * k + 1) * HW) + b_om[2 * k + 1];
    float mval  = sum_part(base + (18 + k   ) * HW) + b_om[18 + k];
    float m = 1.0f / (1.0f + expf(-mval));

    float py = (float)(h - 1 + k / 3) + off_y;
    float px = (float)(w - 1 + k % 3) + off_x;

    float y0f = floorf(py), x0f = floorf(px);
    float ly = py - y0f, lx = px - x0f;
    int y0 = (int)y0f, x0 = (int)x0f;
    int y1 = y0 + 1,   x1 = x0 + 1;

    float vy0 = (y0 >= 0 && y0 < H) ? 1.0f : 0.0f;
    float vy1 = (y1 >= 0 && y1 < H) ? 1.0f : 0.0f;
    float vx0 = (x0 >= 0 && x0 < W) ? 1.0f : 0.0f;
    float vx1 = (x1 >= 0 && x1 < W) ? 1.0f : 0.0f;

    float4 wv;
    wv.x = (1.0f - ly) * (1.0f - lx) * m * vy0 * vx0;
    wv.y = (1.0f - ly) * lx          * m * vy0 * vx1;
    wv.z = ly * (1.0f - lx)          * m * vy1 * vx0;
    wv.w = ly * lx                   * m * vy1 * vx1;

    int4 cv;
    cv.x = min(max(y0, 0), H - 1) * W;
    cv.y = min(max(y1, 0), H - 1) * W;
    cv.z = min(max(x0, 0), W - 1);
    cv.w = min(max(x1, 0), W - 1);

    g_spw[idx] = wv;
    g_spc[idx] = cv;
}

// ---------------- kernel 4: gather v3 (float2 loads, bf16x2 packed stores) ----
// grid 2048, block 256 = 8 warps; warp = one pixel, lane = 2 channels.
__global__ void __launch_bounds__(256) gather_kernel() {
    const int tid  = threadIdx.x;
    const int wid  = tid >> 5;
    const int lane = tid & 31;
    const int px   = (blockIdx.x << 3) + wid;
    const int b    = px >> 12;
    const int hw   = px & 4095;

    const float2* xb2 = reinterpret_cast<const float2*>(g_xhwc + ((size_t)b << 20));
    uint32_t* outp = reinterpret_cast<uint32_t*>(g_cols + (size_t)px * KP);

    #pragma unroll
    for (int k = 0; k < K; ++k) {
        const int gi = (b * K + k) * HW + hw;
        const float4 ww = g_spw[gi];
        const int4   cc = g_spc[gi];
        const int p00 = (cc.x + cc.z) << 7;   // float2 units (128 per px)
        const int p01 = (cc.x + cc.w) << 7;
        const int p10 = (cc.y + cc.z) << 7;
        const int p11 = (cc.y + cc.w) << 7;
        #pragma unroll
        for (int it = 0; it < 4; ++it) {
            const int c2 = (it << 5) + lane;   // float2 index: channels 2*c2, 2*c2+1
            float2 v00 = xb2[p00 + c2], v01 = xb2[p01 + c2];
            float2 v10 = xb2[p10 + c2], v11 = xb2[p11 + c2];
            float va = ww.x * v00.x + ww.y * v01.x + ww.z * v10.x + ww.w * v11.x;
            float vb = ww.x * v00.y + ww.y * v01.y + ww.z * v10.y + ww.w * v11.y;
            __nv_bfloat162 hi2 = __floats2bfloat162_rn(va, vb);
            float2 hif = __bfloat1622float2(hi2);
            __nv_bfloat162 lo2 = __floats2bfloat162_rn(va - hif.x, vb - hif.y);
            outp[k * 128 + c2]            = *reinterpret_cast<uint32_t*>(&hi2);
            outp[1152 + k * 128 + c2]     = *reinterpret_cast<uint32_t*>(&lo2);  // CK/2 = 1152
        }
    }
}

// ---------------- kernel 5: HMMA GEMM  D[o, px] = Wsplit x Cols^T -------------
// grid (2, 64): x = o tile (128 o, FAST dim -> same-px CTAs adjacent for L2),
//               y = px tile (256 px). 256 threads (8 warps), 1 wave (128 CTAs).
// warp tile 64(m) x 64(n): warps laid out 2(m) x 4(n).
__global__ void __launch_bounds__(256, 1)
gemm_kernel(const float* __restrict__ bias, float* __restrict__ out) {
    extern __shared__ __align__(16) char dyn_smem[];
    const uint32_t smem_base = smem_u32(dyn_smem);
    const uint32_t tile0 = (smem_base + 1023u) & ~1023u;   // 1024-aligned stages

    const int tid  = threadIdx.x;
    const int wid  = tid >> 5;
    const int lane = tid & 31;
    const int o_tile = blockIdx.x;            // 0..1
    const int pxb    = blockIdx.y << 8;       // 256 px per CTA

    const int wm = wid & 1;                   // m offset 64*wm
    const int wn = wid >> 1;                  // n offset 64*wn

    const __nv_bfloat16* wA = g_wsplit + (size_t)o_tile * 128 * KP;
    const __nv_bfloat16* cB = g_cols + (size_t)pxb * KP;

    // cp.async geometry: row = tid>>3 (+32 per q), seg = tid&7
    const int r0 = tid >> 3;
    const int sg = tid & 7;

    auto load_chunk = [&](int j) {
        int st = j % STG;
        uint32_t sa = tile0 + st * STAGE_BYTES;
        uint32_t sb = sa + 16384;
        int p  = j / 36;
        int kc = (j - p * 36) * KC;
        int aoff = ((p == 2) ? CK : 0) + kc + sg * 8;
        int boff = ((p == 1) ? CK : 0) + kc + sg * 8;
        #pragma unroll
        for (int q = 0; q < 4; ++q) {        // A: 128 rows
            int r = r0 + (q << 5);
            cp16(sa + sw128((uint32_t)(r * 128 + sg * 16)), wA + (size_t)r * KP + aoff);
        }
        #pragma unroll
        for (int q = 0; q < 8; ++q) {        // B: 256 rows
            int r = r0 + (q << 5);
            cp16(sb + sw128((uint32_t)(r * 128 + sg * 16)), cB + (size_t)r * KP + boff);
        }
        CP_COMMIT();
    };

    float acc[4][8][4];
    #pragma unroll
    for (int i = 0; i < 4; ++i)
        #pragma unroll
        for (int j = 0; j < 8; ++j)
            #pragma unroll
            for (int q = 0; q < 4; ++q) acc[i][j][q] = 0.0f;

    const uint32_t aRow = (uint32_t)(wm * 64 + (lane & 15));
    const uint32_t aCb  = (uint32_t)((lane >> 4) << 4);
    const uint32_t bRow = (uint32_t)(wn * 64 + ((lane >> 4) << 3) + (lane & 7));
    const uint32_t bCb  = (uint32_t)(((lane >> 3) & 1) << 4);

    load_chunk(0);
    load_chunk(1);
    load_chunk(2);

    for (int i = 0; i < NCHUNK; ++i) {
        CP_WAIT2();
        __syncthreads();
        if (i + STG - 1 < NCHUNK) load_chunk(i + STG - 1);

        int st = i % STG;
        uint32_t sa = tile0 + st * STAGE_BYTES;
        uint32_t sb = sa + 16384;

        #pragma unroll
        for (int kk = 0; kk < 4; ++kk) {
            uint32_t a[4][4], b[8][2];
            #pragma unroll
            for (int mf = 0; mf < 4; ++mf)
                ldsm_x4(a[mf], sa + sw128((aRow + mf * 16) * 128 + aCb + kk * 32));
            #pragma unroll
            for (int half = 0; half < 4; ++half) {
                uint32_t r[4];
                ldsm_x4(r, sb + sw128((bRow + half * 16) * 128 + bCb + kk * 32));
                b[2 * half][0] = r[0]; b[2 * half][1] = r[1];
                b[2 * half + 1][0] = r[2]; b[2 * half + 1][1] = r[3];
            }
            #pragma unroll
            for (int mf = 0; mf < 4; ++mf)
                #pragma unroll
                for (int nf = 0; nf < 8; ++nf)
                    mma16816(acc[mf][nf], a[mf], b[nf]);
        }
    }
    CP_WAIT0();

    // ---- epilogue: direct register -> gmem stores -----------------------------
    const int bb  = pxb >> 12;
    const int hw0 = pxb & 4095;
    const int oBase = o_tile * 128 + wm * 64 + (lane >> 2);
    const int nBase = hw0 + wn * 64 + (lane & 3) * 2;

    #pragma unroll
    for (int mf = 0; mf < 4; ++mf) {
        int o0 = oBase + mf * 16;
        float bz0 = __ldg(bias + o0);
        float bz8 = __ldg(bias + o0 + 8);
        float* op0 = out + (bb << 20) + (o0 << 12) + nBase;
        float* op8 = op0 + (8 << 12);
        #pragma unroll
        for (int nf = 0; nf < 8; ++nf) {
            float2 v0 = make_float2(acc[mf][nf][0] + bz0, acc[mf][nf][1] + bz0);
            float2 v1 = make_float2(acc[mf][nf][2] + bz8, acc[mf][nf][3] + bz8);
            *reinterpret_cast<float2*>(op0 + nf * 8) = v0;
            *reinterpret_cast<float2*>(op8 + nf * 8) = v1;
        }
    }
}

// ---------------- launch ------------------------------------------------------
extern "C" void kernel_launch(void* const* d_in, const int* in_sizes, int n_in,
                              void* d_out, int out_size) {
    const float* x      = (const float*)d_in[0];   // (4,256,64,64)
    const float* w_om   = (const float*)d_in[1];   // (27,256,3,3)
    const float* b_om   = (const float*)d_in[2];   // (27,)
    const float* weight = (const float*)d_in[3];   // (256,256,3,3)
    const float* bias   = (const float*)d_in[4];   // (256,)
    float* out = (float*)d_out;                    // (4,256,64,64)

    cudaFuncSetAttribute(gemm_kernel, cudaFuncAttributeMaxDynamicSharedMemorySize, SMEM_DYN);

    prep_kernel<<<4924, 256>>>(x, w_om, weight);
    offset_conv_kernel<<<dim3(8, 4, 8), 256>>>(x);
    params_kernel<<<144, 1024>>>(b_om);
    gather_kernel<<<2048, 256>>>();
    gemm_kernel<<<dim3(2, 64), 256, SMEM_DYN>>>(bias, out);
}

// round 9
// speedup vs baseline: 4.5829x; 1.0216x over previous
#include <cuda_runtime.h>
#include <cuda_bf16.h>
#include <math.h>
#include <cstdint>

// Problem constants
#define B   4
#define C   256
#define H   64
#define W   64
#define O   256
#define K   9           // 3x3
#define HW  4096        // H*W
#define CK  2304        // C*K
#define KP  4608        // 2*CK (hi | lo)
#define NPIX 16384      // B*H*W

// GEMM config
#define KC      64      // K elems per chunk (bf16) = 128B rows
#define NCHUNK  108     // 3 passes x (2304/64)
#define STG     4       // cp.async pipeline stages
#define STAGE_BYTES 49152   // A 16KB + B 32KB
#define SMEM_DYN (1024 + STG * STAGE_BYTES)

#define NSEG 8                       // channel segments in offset conv
#define SEG_STRIDE (B * 27 * HW)     // per-segment partial block

// ---------------- scratch (__device__ globals; no allocs allowed) -------------
__device__ float  g_part[NSEG * SEG_STRIDE];        // offset-conv partials
__device__ float  g_xhwc[(size_t)NPIX * C];         // x in NHWC
__device__ __nv_bfloat16 g_wsplit[O * KP];          // [o][hi k-major | lo k-major]
__device__ __nv_bfloat16 g_cols[(size_t)NPIX * KP]; // [px][hi k-major | lo k-major]

// ---------------- PTX helpers -------------------------------------------------
__device__ __forceinline__ uint32_t smem_u32(const void* p) {
    uint32_t a;
    asm("{ .reg .u64 t; cvta.to.shared.u64 t, %1; cvt.u32.u64 %0, t; }" : "=r"(a) : "l"(p));
    return a;
}
__device__ __forceinline__ void cp16(uint32_t dst, const void* src) {
    asm volatile("cp.async.cg.shared.global [%0], [%1], 16;" :: "r"(dst), "l"(src) : "memory");
}
#define CP_COMMIT() asm volatile("cp.async.commit_group;" ::: "memory")
#define CP_WAIT2()  asm volatile("cp.async.wait_group 2;" ::: "memory")
#define CP_WAIT0()  asm volatile("cp.async.wait_group 0;" ::: "memory")

__device__ __forceinline__ uint32_t sw128(uint32_t off) { return off ^ ((off >> 3) & 0x70); }

__device__ __forceinline__ void ldsm_x4(uint32_t* r, uint32_t addr) {
    asm volatile("ldmatrix.sync.aligned.m8n8.x4.shared.b16 {%0,%1,%2,%3}, [%4];"
        : "=r"(r[0]), "=r"(r[1]), "=r"(r[2]), "=r"(r[3]) : "r"(addr));
}
__device__ __forceinline__ void mma16816(float* d, const uint32_t* a, const uint32_t* b) {
    asm volatile("mma.sync.aligned.m16n8k16.row.col.f32.bf16.bf16.f32 "
        "{%0,%1,%2,%3}, {%4,%5,%6,%7}, {%8,%9}, {%0,%1,%2,%3};"
        : "+f"(d[0]), "+f"(d[1]), "+f"(d[2]), "+f"(d[3])
        : "r"(a[0]), "r"(a[1]), "r"(a[2]), "r"(a[3]), "r"(b[0]), "r"(b[1]));
}

// ---------------- kernel 1: prep_all -------------------------------------------
// grid 4928 x 256 threads:
//   [0, 256)     : offset conv (FFMA-bound; scheduled first to overlap mem blocks)
//   [256, 4352)  : NCHW->NHWC transpose
//   [4352, 4928) : wsplit (576 blocks x 256 threads x 4 elems)
__global__ void __launch_bounds__(256) prep_all_kernel(const float* __restrict__ x,
                                                       const float* __restrict__ w_om,
                                                       const float* __restrict__ weight) {
    __shared__ __align__(16) float sbuf[8064];       // 32 KB: ws | transpose tile
    const int bid = blockIdx.x;
    const int tid = threadIdx.x;

    if (bid < 256) {
        // ---- offset conv: warp = one h row of one 32-ch segment ----
        const int wid = tid >> 5;
        const int lane = tid & 31;
        const int cs = bid >> 5;
        const int b  = (bid >> 3) & 3;
        const int h  = ((bid & 7) << 3) + wid;
        const int c0 = cs << 5;

        // stage repacked weights: ws[ci*252 + j*28 + oc] = w_om[oc*CK + (c0+ci)*9 + j]
        for (int i = tid; i < 8064; i += 256) {
            int ci = i / 252;
            int r  = i - ci * 252;
            int j  = r / 28;
            int oc = r - j * 28;
            sbuf[i] = (oc < 27) ? w_om[oc * CK + (c0 + ci) * 9 + j] : 0.0f;
        }
        __syncthreads();

        float acc_e[28], acc_o[28];
        #pragma unroll
        for (int i = 0; i < 28; ++i) { acc_e[i] = 0.0f; acc_o[i] = 0.0f; }

        const unsigned FULL = 0xFFFFFFFFu;

        for (int ci = 0; ci < 32; ++ci) {
            const int c = c0 + ci;
            const float* xp = x + (((b << 8) + c) << 12) + (h << 6) + (lane << 1);

            float2 r0 = (h > 0)     ? *reinterpret_cast<const float2*>(xp - 64) : make_float2(0.f, 0.f);
            float2 r1 =               *reinterpret_cast<const float2*>(xp);
            float2 r2 = (h < H - 1) ? *reinterpret_cast<const float2*>(xp + 64) : make_float2(0.f, 0.f);

            float le0 = __shfl_up_sync(FULL, r0.y, 1); if (lane == 0) le0 = 0.f;
            float le1 = __shfl_up_sync(FULL, r1.y, 1); if (lane == 0) le1 = 0.f;
            float le2 = __shfl_up_sync(FULL, r2.y, 1); if (lane == 0) le2 = 0.f;
            float ri0 = __shfl_down_sync(FULL, r0.x, 1); if (lane == 31) ri0 = 0.f;
            float ri1 = __shfl_down_sync(FULL, r1.x, 1); if (lane == 31) ri1 = 0.f;
            float ri2 = __shfl_down_sync(FULL, r2.x, 1); if (lane == 31) ri2 = 0.f;

            float xe[9], xo[9];
            xe[0] = le0;  xo[0] = r0.x;
            xe[1] = r0.x; xo[1] = r0.y;
            xe[2] = r0.y; xo[2] = ri0;
            xe[3] = le1;  xo[3] = r1.x;
            xe[4] = r1.x; xo[4] = r1.y;
            xe[5] = r1.y; xo[5] = ri1;
            xe[6] = le2;  xo[6] = r2.x;
            xe[7] = r2.x; xo[7] = r2.y;
            xe[8] = r2.y; xo[8] = ri2;

            const float4* w4 = reinterpret_cast<const float4*>(sbuf + ci * 252);
            #pragma unroll
            for (int j = 0; j < 9; ++j) {
                float ve = xe[j], vo = xo[j];
                #pragma unroll
                for (int q = 0; q < 7; ++q) {
                    float4 wv = w4[j * 7 + q];   // broadcast LDS.128
                    acc_e[q * 4 + 0] = fmaf(ve, wv.x, acc_e[q * 4 + 0]);
                    acc_o[q * 4 + 0] = fmaf(vo, wv.x, acc_o[q * 4 + 0]);
                    acc_e[q * 4 + 1] = fmaf(ve, wv.y, acc_e[q * 4 + 1]);
                    acc_o[q * 4 + 1] = fmaf(vo, wv.y, acc_o[q * 4 + 1]);
                    acc_e[q * 4 + 2] = fmaf(ve, wv.z, acc_e[q * 4 + 2]);
                    acc_o[q * 4 + 2] = fmaf(vo, wv.z, acc_o[q * 4 + 2]);
                    acc_e[q * 4 + 3] = fmaf(ve, wv.w, acc_e[q * 4 + 3]);
                    acc_o[q * 4 + 3] = fmaf(vo, wv.w, acc_o[q * 4 + 3]);
                }
            }
        }

        float* pp = g_part + cs * SEG_STRIDE + (b * 27) * HW + (h << 6) + (lane << 1);
        #pragma unroll
        for (int oc = 0; oc < 27; ++oc)
            *reinterpret_cast<float2*>(pp + oc * HW) = make_float2(acc_e[oc], acc_o[oc]);

    } else if (bid < 4352) {
        // ---- NCHW -> NHWC transpose, 32px x 32ch tile ----
        float (*t)[33] = reinterpret_cast<float(*)[33]>(sbuf);
        const int tbid = bid - 256;
        const int hw0 = (tbid & 127) << 5;
        const int c0  = ((tbid >> 7) & 7) << 5;
        const int b   = tbid >> 10;
        const int tx = tid & 31, ty = tid >> 5;
        #pragma unroll
        for (int j = 0; j < 4; ++j) {
            int c = c0 + ty + 8 * j;
            t[ty + 8 * j][tx] = x[(((b << 8) + c) << 12) + hw0 + tx];
        }
        __syncthreads();
        #pragma unroll
        for (int j = 0; j < 4; ++j) {
            int hw = hw0 + ty + 8 * j;
            g_xhwc[(size_t)(((b << 12) + hw) << 8) + c0 + tx] = t[tx][ty + 8 * j];
        }
    } else {
        // ---- wsplit: bf16 hi/lo, k-major ----
        int i = (bid - 4352) * 1024 + tid * 4;  // < 589824
        const float4 v4 = *reinterpret_cast<const float4*>(weight + i);
        const float vs[4] = { v4.x, v4.y, v4.z, v4.w };
        #pragma unroll
        for (int q = 0; q < 4; ++q) {
            float v = vs[q];
            __nv_bfloat16 hi = __float2bfloat16(v);
            __nv_bfloat16 lo = __float2bfloat16(v - __bfloat162float(hi));
            int e = i + q;
            int o = e / CK, r = e - o * CK;
            int c = r / 9, k = r - c * 9;
            int ck = k * 256 + c;                // k-major
            g_wsplit[o * KP + ck]      = hi;
            g_wsplit[o * KP + CK + ck] = lo;
        }
    }
}

// ---------------- kernel 2: fused params + gather -----------------------------
// grid 2048, block 256 = 8 px. Phase 1: 72 threads compute the 8x9 sampling
// params into smem. Phase 2: warp = one pixel, lane = 2 channels (float2/bf16x2).
__global__ void __launch_bounds__(256) gather_kernel(const float* __restrict__ b_om) {
    __shared__ float4 s_ww[8][9];
    __shared__ int4   s_cc[8][9];

    const int tid  = threadIdx.x;
    const int pix0 = blockIdx.x << 3;
    const int b    = pix0 >> 12;         // 8 px never straddle a batch (4096%8==0)

    // ---- phase 1: params for 8 px x 9 taps ----
    if (tid < 72) {
        const int p = tid / 9;
        const int k = tid - p * 9;
        const int hw = (pix0 + p) & 4095;
        const int h  = hw >> 6;
        const int w  = hw & 63;
        const int base = b * 27 * HW + hw;

        float off_y = b_om[2 * k], off_x = b_om[2 * k + 1], mval = b_om[18 + k];
        #pragma unroll
        for (int cs = 0; cs < NSEG; ++cs) {
            const float* pp = g_part + cs * SEG_STRIDE + base;
            off_y += pp[(2 * k) * HW];
            off_x += pp[(2 * k + 1) * HW];
            mval  += pp[(18 + k) * HW];
        }
        float m = 1.0f / (1.0f + expf(-mval));

        float py = (float)(h - 1 + k / 3) + off_y;
        float px = (float)(w - 1 + k % 3) + off_x;

        float y0f = floorf(py), x0f = floorf(px);
        float ly = py - y0f, lx = px - x0f;
        int y0 = (int)y0f, x0 = (int)x0f;
        int y1 = y0 + 1,   x1 = x0 + 1;

        float vy0 = (y0 >= 0 && y0 < H) ? 1.0f : 0.0f;
        float vy1 = (y1 >= 0 && y1 < H) ? 1.0f : 0.0f;
        float vx0 = (x0 >= 0 && x0 < W) ? 1.0f : 0.0f;
        float vx1 = (x1 >= 0 && x1 < W) ? 1.0f : 0.0f;

        float4 wv;
        wv.x = (1.0f - ly) * (1.0f - lx) * m * vy0 * vx0;
        wv.y = (1.0f - ly) * lx          * m * vy0 * vx1;
        wv.z = ly * (1.0f - lx)          * m * vy1 * vx0;
        wv.w = ly * lx                   * m * vy1 * vx1;

        int4 cv;
        cv.x = min(max(y0, 0), H - 1) * W;
        cv.y = min(max(y1, 0), H - 1) * W;
        cv.z = min(max(x0, 0), W - 1);
        cv.w = min(max(x1, 0), W - 1);

        s_ww[p][k] = wv;
        s_cc[p][k] = cv;
    }
    __syncthreads();

    // ---- phase 2: gather ----
    const int wid  = tid >> 5;
    const int lane = tid & 31;
    const int px   = pix0 + wid;

    const float2* xb2 = reinterpret_cast<const float2*>(g_xhwc + ((size_t)b << 20));
    uint32_t* outp = reinterpret_cast<uint32_t*>(g_cols + (size_t)px * KP);

    #pragma unroll
    for (int k = 0; k < K; ++k) {
        const float4 ww = s_ww[wid][k];
        const int4   cc = s_cc[wid][k];
        const int p00 = (cc.x + cc.z) << 7;   // float2 units (128 per px)
        const int p01 = (cc.x + cc.w) << 7;
        const int p10 = (cc.y + cc.z) << 7;
        const int p11 = (cc.y + cc.w) << 7;
        #pragma unroll
        for (int it = 0; it < 4; ++it) {
            const int c2 = (it << 5) + lane;   // float2 index: channels 2*c2, 2*c2+1
            float2 v00 = xb2[p00 + c2], v01 = xb2[p01 + c2];
            float2 v10 = xb2[p10 + c2], v11 = xb2[p11 + c2];
            float va = ww.x * v00.x + ww.y * v01.x + ww.z * v10.x + ww.w * v11.x;
            float vb = ww.x * v00.y + ww.y * v01.y + ww.z * v10.y + ww.w * v11.y;
            __nv_bfloat162 hi2 = __floats2bfloat162_rn(va, vb);
            float2 hif = __bfloat1622float2(hi2);
            __nv_bfloat162 lo2 = __floats2bfloat162_rn(va - hif.x, vb - hif.y);
            outp[k * 128 + c2]        = *reinterpret_cast<uint32_t*>(&hi2);
            outp[1152 + k * 128 + c2] = *reinterpret_cast<uint32_t*>(&lo2);  // CK/2
        }
    }
}

// ---------------- kernel 3: HMMA GEMM  D[o, px] = Wsplit x Cols^T -------------
// grid (2, 64): x = o tile (128 o, FAST dim -> same-px CTAs adjacent for L2),
//               y = px tile (256 px). 256 threads (8 warps), 1 wave (128 CTAs).
// warp tile 64(m) x 64(n): warps laid out 2(m) x 4(n).
__global__ void __launch_bounds__(256, 1)
gemm_kernel(const float* __restrict__ bias, float* __restrict__ out) {
    extern __shared__ __align__(16) char dyn_smem[];
    const uint32_t smem_base = smem_u32(dyn_smem);
    const uint32_t tile0 = (smem_base + 1023u) & ~1023u;   // 1024-aligned stages

    const int tid  = threadIdx.x;
    const int wid  = tid >> 5;
    const int lane = tid & 31;
    const int o_tile = blockIdx.x;            // 0..1
    const int pxb    = blockIdx.y << 8;       // 256 px per CTA

    const int wm = wid & 1;                   // m offset 64*wm
    const int wn = wid >> 1;                  // n offset 64*wn

    const __nv_bfloat16* wA = g_wsplit + (size_t)o_tile * 128 * KP;
    const __nv_bfloat16* cB = g_cols + (size_t)pxb * KP;

    const int r0 = tid >> 3;
    const int sg = tid & 7;

    auto load_chunk = [&](int j) {
        int st = j % STG;
        uint32_t sa = tile0 + st * STAGE_BYTES;
        uint32_t sb = sa + 16384;
        int p  = j / 36;
        int kc = (j - p * 36) * KC;
        int aoff = ((p == 2) ? CK : 0) + kc + sg * 8;
        int boff = ((p == 1) ? CK : 0) + kc + sg * 8;
        #pragma unroll
        for (int q = 0; q < 4; ++q) {        // A: 128 rows
            int r = r0 + (q << 5);
            cp16(sa + sw128((uint32_t)(r * 128 + sg * 16)), wA + (size_t)r * KP + aoff);
        }
        #pragma unroll
        for (int q = 0; q < 8; ++q) {        // B: 256 rows
            int r = r0 + (q << 5);
            cp16(sb + sw128((uint32_t)(r * 128 + sg * 16)), cB + (size_t)r * KP + boff);
        }
        CP_COMMIT();
    };

    float acc[4][8][4];
    #pragma unroll
    for (int i = 0; i < 4; ++i)
        #pragma unroll
        for (int j = 0; j < 8; ++j)
            #pragma unroll
            for (int q = 0; q < 4; ++q) acc[i][j][q] = 0.0f;

    const uint32_t aRow = (uint32_t)(wm * 64 + (lane & 15));
    const uint32_t aCb  = (uint32_t)((lane >> 4) << 4);
    const uint32_t bRow = (uint32_t)(wn * 64 + ((lane >> 4) << 3) + (lane & 7));
    const uint32_t bCb  = (uint32_t)(((lane >> 3) & 1) << 4);

    load_chunk(0);
    load_chunk(1);
    load_chunk(2);

    for (int i = 0; i < NCHUNK; ++i) {
        CP_WAIT2();
        __syncthreads();
        if (i + STG - 1 < NCHUNK) load_chunk(i + STG - 1);

        int st = i % STG;
        uint32_t sa = tile0 + st * STAGE_BYTES;
        uint32_t sb = sa + 16384;

        #pragma unroll
        for (int kk = 0; kk < 4; ++kk) {
            uint32_t a[4][4], b[8][2];
            #pragma unroll
            for (int mf = 0; mf < 4; ++mf)
                ldsm_x4(a[mf], sa + sw128((aRow + mf * 16) * 128 + aCb + kk * 32));
            #pragma unroll
            for (int half = 0; half < 4; ++half) {
                uint32_t r[4];
                ldsm_x4(r, sb + sw128((bRow + half * 16) * 128 + bCb + kk * 32));
                b[2 * half][0] = r[0]; b[2 * half][1] = r[1];
                b[2 * half + 1][0] = r[2]; b[2 * half + 1][1] = r[3];
            }
            #pragma unroll
            for (int mf = 0; mf < 4; ++mf)
                #pragma unroll
                for (int nf = 0; nf < 8; ++nf)
                    mma16816(acc[mf][nf], a[mf], b[nf]);
        }
    }
    CP_WAIT0();

    // ---- epilogue: direct register -> gmem stores -----------------------------
    const int bb  = pxb >> 12;
    const int hw0 = pxb & 4095;
    const int oBase = o_tile * 128 + wm * 64 + (lane >> 2);
    const int nBase = hw0 + wn * 64 + (lane & 3) * 2;

    #pragma unroll
    for (int mf = 0; mf < 4; ++mf) {
        int o0 = oBase + mf * 16;
        float bz0 = __ldg(bias + o0);
        float bz8 = __ldg(bias + o0 + 8);
        float* op0 = out + (bb << 20) + (o0 << 12) + nBase;
        float* op8 = op0 + (8 << 12);
        #pragma unroll
        for (int nf = 0; nf < 8; ++nf) {
            float2 v0 = make_float2(acc[mf][nf][0] + bz0, acc[mf][nf][1] + bz0);
            float2 v1 = make_float2(acc[mf][nf][2] + bz8, acc[mf][nf][3] + bz8);
            *reinterpret_cast<float2*>(op0 + nf * 8) = v0;
            *reinterpret_cast<float2*>(op8 + nf * 8) = v1;
        }
    }
}

// ---------------- launch ------------------------------------------------------
extern "C" void kernel_launch(void* const* d_in, const int* in_sizes, int n_in,
                              void* d_out, int out_size) {
    const float* x      = (const float*)d_in[0];   // (4,256,64,64)
    const float* w_om   = (const float*)d_in[1];   // (27,256,3,3)
    const float* b_om   = (const float*)d_in[2];   // (27,)
    const float* weight = (const float*)d_in[3];   // (256,256,3,3)
    const float* bias   = (const float*)d_in[4];   // (256,)
    float* out = (float*)d_out;                    // (4,256,64,64)

    cudaFuncSetAttribute(gemm_kernel, cudaFuncAttributeMaxDynamicSharedMemorySize, SMEM_DYN);

    prep_all_kernel<<<4928, 256>>>(x, w_om, weight);
    gather_kernel<<<2048, 256>>>(b_om);
    gemm_kernel<<<dim3(2, 64), 256, SMEM_DYN>>>(bias, out);
}

// round 10
// speedup vs baseline: 7.7219x; 1.6849x over previous
#include <cuda_runtime.h>
#include <cuda_bf16.h>
#include <cuda_fp16.h>
#include <math.h>
#include <cstdint>

// Problem constants
#define B   4
#define C   256
#define H   64
#define W   64
#define O   256
#define K   9           // 3x3
#define HW  4096        // H*W
#define CK  2304        // C*K
#define NPIX 16384      // B*H*W

// GEMM config (1-pass fp16)
#define KC      64      // K elems per chunk (fp16) = 128B rows
#define NCHUNK  36      // 2304/64
#define STG     4       // cp.async pipeline stages
#define STAGE_BYTES 49152   // A 16KB + B 32KB
#define SMEM_DYN (1024 + STG * STAGE_BYTES)

#define NSEG 8                       // channel segments in offset conv
#define SEG_STRIDE (B * 27 * HW)     // per-segment partial block

// ---------------- scratch (__device__ globals; no allocs allowed) -------------
__device__ float  g_part[NSEG * SEG_STRIDE];      // offset-conv partials
__device__ float  g_xhwc[(size_t)NPIX * C];       // x in NHWC
__device__ __half g_whalf[O * CK];                // [o][k-major fp16]
__device__ __half g_cols[(size_t)NPIX * CK];      // [px][k-major fp16]

// ---------------- PTX helpers -------------------------------------------------
__device__ __forceinline__ uint32_t smem_u32(const void* p) {
    uint32_t a;
    asm("{ .reg .u64 t; cvta.to.shared.u64 t, %1; cvt.u32.u64 %0, t; }" : "=r"(a) : "l"(p));
    return a;
}
__device__ __forceinline__ void cp16(uint32_t dst, const void* src) {
    asm volatile("cp.async.cg.shared.global [%0], [%1], 16;" :: "r"(dst), "l"(src) : "memory");
}
#define CP_COMMIT() asm volatile("cp.async.commit_group;" ::: "memory")
#define CP_WAIT2()  asm volatile("cp.async.wait_group 2;" ::: "memory")
#define CP_WAIT0()  asm volatile("cp.async.wait_group 0;" ::: "memory")

__device__ __forceinline__ uint32_t sw128(uint32_t off) { return off ^ ((off >> 3) & 0x70); }

__device__ __forceinline__ void ldsm_x4(uint32_t* r, uint32_t addr) {
    asm volatile("ldmatrix.sync.aligned.m8n8.x4.shared.b16 {%0,%1,%2,%3}, [%4];"
        : "=r"(r[0]), "=r"(r[1]), "=r"(r[2]), "=r"(r[3]) : "r"(addr));
}
__device__ __forceinline__ void mma16816(float* d, const uint32_t* a, const uint32_t* b) {
    asm volatile("mma.sync.aligned.m16n8k16.row.col.f32.f16.f16.f32 "
        "{%0,%1,%2,%3}, {%4,%5,%6,%7}, {%8,%9}, {%0,%1,%2,%3};"
        : "+f"(d[0]), "+f"(d[1]), "+f"(d[2]), "+f"(d[3])
        : "r"(a[0]), "r"(a[1]), "r"(a[2]), "r"(a[3]), "r"(b[0]), "r"(b[1]));
}
// packed f32x2 FMA (base sm_100+ feature; valid at compute_103)
__device__ __forceinline__ void fma2(uint64_t& d, uint64_t a, uint64_t b) {
    asm("fma.rn.f32x2 %0, %1, %2, %3;" : "=l"(d) : "l"(a), "l"(b), "l"(d));
}
__device__ __forceinline__ uint64_t bcast2(float v) {
    uint64_t d; uint32_t u = __float_as_uint(v);
    asm("mov.b64 %0, {%1, %1};" : "=l"(d) : "r"(u));
    return d;
}
__device__ __forceinline__ float2 unpack2(uint64_t v) {
    uint32_t lo, hi;
    asm("mov.b64 {%0, %1}, %2;" : "=r"(lo), "=r"(hi) : "l"(v));
    return make_float2(__uint_as_float(lo), __uint_as_float(hi));
}

// ---------------- kernel 1: prep_all -------------------------------------------
// grid 4928 x 256 threads:
//   [0, 256)     : offset conv (FFMA2-packed; scheduled first to overlap mem blocks)
//   [256, 4352)  : NCHW->NHWC transpose
//   [4352, 4928) : wsplit -> fp16 k-major
__global__ void __launch_bounds__(256) prep_all_kernel(const float* __restrict__ x,
                                                       const float* __restrict__ w_om,
                                                       const float* __restrict__ weight) {
    __shared__ __align__(16) float sbuf[8064];       // 32 KB: ws | transpose tile
    const int bid = blockIdx.x;
    const int tid = threadIdx.x;

    if (bid < 256) {
        // ---- offset conv: warp = one h row of one 32-ch segment ----
        const int wid = tid >> 5;
        const int lane = tid & 31;
        const int cs = bid >> 5;
        const int b  = (bid >> 3) & 3;
        const int h  = ((bid & 7) << 3) + wid;
        const int c0 = cs << 5;

        // stage repacked weights: ws[ci*252 + j*28 + oc] = w_om[oc*CK + (c0+ci)*9 + j]
        for (int i = tid; i < 8064; i += 256) {
            int ci = i / 252;
            int r  = i - ci * 252;
            int j  = r / 28;
            int oc = r - j * 28;
            sbuf[i] = (oc < 27) ? w_om[oc * CK + (c0 + ci) * 9 + j] : 0.0f;
        }
        __syncthreads();

        // packed accumulators: acc2e[q] = (oc=2q, oc=2q+1) for even px; acc2o for odd px
        uint64_t acc2e[14], acc2o[14];
        #pragma unroll
        for (int i = 0; i < 14; ++i) { acc2e[i] = 0ull; acc2o[i] = 0ull; }

        const unsigned FULL = 0xFFFFFFFFu;

        for (int ci = 0; ci < 32; ++ci) {
            const int c = c0 + ci;
            const float* xp = x + (((b << 8) + c) << 12) + (h << 6) + (lane << 1);

            float2 r0 = (h > 0)     ? *reinterpret_cast<const float2*>(xp - 64) : make_float2(0.f, 0.f);
            float2 r1 =               *reinterpret_cast<const float2*>(xp);
            float2 r2 = (h < H - 1) ? *reinterpret_cast<const float2*>(xp + 64) : make_float2(0.f, 0.f);

            float le0 = __shfl_up_sync(FULL, r0.y, 1); if (lane == 0) le0 = 0.f;
            float le1 = __shfl_up_sync(FULL, r1.y, 1); if (lane == 0) le1 = 0.f;
            float le2 = __shfl_up_sync(FULL, r2.y, 1); if (lane == 0) le2 = 0.f;
            float ri0 = __shfl_down_sync(FULL, r0.x, 1); if (lane == 31) ri0 = 0.f;
            float ri1 = __shfl_down_sync(FULL, r1.x, 1); if (lane == 31) ri1 = 0.f;
            float ri2 = __shfl_down_sync(FULL, r2.x, 1); if (lane == 31) ri2 = 0.f;

            float xe[9], xo[9];
            xe[0] = le0;  xo[0] = r0.x;
            xe[1] = r0.x; xo[1] = r0.y;
            xe[2] = r0.y; xo[2] = ri0;
            xe[3] = le1;  xo[3] = r1.x;
            xe[4] = r1.x; xo[4] = r1.y;
            xe[5] = r1.y; xo[5] = ri1;
            xe[6] = le2;  xo[6] = r2.x;
            xe[7] = r2.x; xo[7] = r2.y;
            xe[8] = r2.y; xo[8] = ri2;

            // weights as packed pairs: 7 x LDS.128 per tap row
            const ulonglong2* w16 = reinterpret_cast<const ulonglong2*>(sbuf + ci * 252);
            #pragma unroll
            for (int j = 0; j < 9; ++j) {
                uint64_t vve = bcast2(xe[j]);
                uint64_t vvo = bcast2(xo[j]);
                #pragma unroll
                for (int t = 0; t < 7; ++t) {
                    ulonglong2 wp = w16[j * 7 + t];
                    fma2(acc2e[2 * t],     vve, wp.x);
                    fma2(acc2e[2 * t + 1], vve, wp.y);
                    fma2(acc2o[2 * t],     vvo, wp.x);
                    fma2(acc2o[2 * t + 1], vvo, wp.y);
                }
            }
        }

        float* pp = g_part + cs * SEG_STRIDE + (b * 27) * HW + (h << 6) + (lane << 1);
        #pragma unroll
        for (int q = 0; q < 14; ++q) {
            float2 e = unpack2(acc2e[q]);
            float2 o = unpack2(acc2o[q]);
            *reinterpret_cast<float2*>(pp + (2 * q) * HW) = make_float2(e.x, o.x);
            if (2 * q + 1 < 27)
                *reinterpret_cast<float2*>(pp + (2 * q + 1) * HW) = make_float2(e.y, o.y);
        }

    } else if (bid < 4352) {
        // ---- NCHW -> NHWC transpose, 32px x 32ch tile ----
        float (*t)[33] = reinterpret_cast<float(*)[33]>(sbuf);
        const int tbid = bid - 256;
        const int hw0 = (tbid & 127) << 5;
        const int c0  = ((tbid >> 7) & 7) << 5;
        const int b   = tbid >> 10;
        const int tx = tid & 31, ty = tid >> 5;
        #pragma unroll
        for (int j = 0; j < 4; ++j) {
            int c = c0 + ty + 8 * j;
            t[ty + 8 * j][tx] = x[(((b << 8) + c) << 12) + hw0 + tx];
        }
        __syncthreads();
        #pragma unroll
        for (int j = 0; j < 4; ++j) {
            int hw = hw0 + ty + 8 * j;
            g_xhwc[(size_t)(((b << 12) + hw) << 8) + c0 + tx] = t[tx][ty + 8 * j];
        }
    } else {
        // ---- wsplit: fp16, k-major ----
        int i = (bid - 4352) * 1024 + tid * 4;  // < 589824
        const float4 v4 = *reinterpret_cast<const float4*>(weight + i);
        const float vs[4] = { v4.x, v4.y, v4.z, v4.w };
        #pragma unroll
        for (int q = 0; q < 4; ++q) {
            int e = i + q;
            int o = e / CK, r = e - o * CK;
            int c = r / 9, k = r - c * 9;
            g_whalf[o * CK + k * 256 + c] = __float2half_rn(vs[q]);
        }
    }
}

// ---------------- kernel 2: fused params + gather (fp16 cols) ------------------
// grid 2048, block 256 = 8 px. Phase 1: 72 threads compute the 8x9 sampling
// params into smem. Phase 2: warp = one pixel, lane = 2 channels (float2/half2).
__global__ void __launch_bounds__(256) gather_kernel(const float* __restrict__ b_om) {
    __shared__ float4 s_ww[8][9];
    __shared__ int4   s_cc[8][9];

    const int tid  = threadIdx.x;
    const int pix0 = blockIdx.x << 3;
    const int b    = pix0 >> 12;

    if (tid < 72) {
        const int p = tid / 9;
        const int k = tid - p * 9;
        const int hw = (pix0 + p) & 4095;
        const int h  = hw >> 6;
        const int w  = hw & 63;
        const int base = b * 27 * HW + hw;

        float off_y = b_om[2 * k], off_x = b_om[2 * k + 1], mval = b_om[18 + k];
        #pragma unroll
        for (int cs = 0; cs < NSEG; ++cs) {
            const float* pp = g_part + cs * SEG_STRIDE + base;
            off_y += pp[(2 * k) * HW];
            off_x += pp[(2 * k + 1) * HW];
            mval  += pp[(18 + k) * HW];
        }
        float m = 1.0f / (1.0f + expf(-mval));

        float py = (float)(h - 1 + k / 3) + off_y;
        float px = (float)(w - 1 + k % 3) + off_x;

        float y0f = floorf(py), x0f = floorf(px);
        float ly = py - y0f, lx = px - x0f;
        int y0 = (int)y0f, x0 = (int)x0f;
        int y1 = y0 + 1,   x1 = x0 + 1;

        float vy0 = (y0 >= 0 && y0 < H) ? 1.0f : 0.0f;
        float vy1 = (y1 >= 0 && y1 < H) ? 1.0f : 0.0f;
        float vx0 = (x0 >= 0 && x0 < W) ? 1.0f : 0.0f;
        float vx1 = (x1 >= 0 && x1 < W) ? 1.0f : 0.0f;

        float4 wv;
        wv.x = (1.0f - ly) * (1.0f - lx) * m * vy0 * vx0;
        wv.y = (1.0f - ly) * lx          * m * vy0 * vx1;
        wv.z = ly * (1.0f - lx)          * m * vy1 * vx0;
        wv.w = ly * lx                   * m * vy1 * vx1;

        int4 cv;
        cv.x = min(max(y0, 0), H - 1) * W;
        cv.y = min(max(y1, 0), H - 1) * W;
        cv.z = min(max(x0, 0), W - 1);
        cv.w = min(max(x1, 0), W - 1);

        s_ww[p][k] = wv;
        s_cc[p][k] = cv;
    }
    __syncthreads();

    const int wid  = tid >> 5;
    const int lane = tid & 31;
    const int px   = pix0 + wid;

    const float2* xb2 = reinterpret_cast<const float2*>(g_xhwc + ((size_t)b << 20));
    uint32_t* outp = reinterpret_cast<uint32_t*>(g_cols + (size_t)px * CK);

    #pragma unroll
    for (int k = 0; k < K; ++k) {
        const float4 ww = s_ww[wid][k];
        const int4   cc = s_cc[wid][k];
        const int p00 = (cc.x + cc.z) << 7;   // float2 units (128 per px)
        const int p01 = (cc.x + cc.w) << 7;
        const int p10 = (cc.y + cc.z) << 7;
        const int p11 = (cc.y + cc.w) << 7;
        #pragma unroll
        for (int it = 0; it < 4; ++it) {
            const int c2 = (it << 5) + lane;   // float2 index: channels 2*c2, 2*c2+1
            float2 v00 = xb2[p00 + c2], v01 = xb2[p01 + c2];
            float2 v10 = xb2[p10 + c2], v11 = xb2[p11 + c2];
            float va = ww.x * v00.x + ww.y * v01.x + ww.z * v10.x + ww.w * v11.x;
            float vb = ww.x * v00.y + ww.y * v01.y + ww.z * v10.y + ww.w * v11.y;
            __half2 h2 = __floats2half2_rn(va, vb);
            outp[k * 128 + c2] = *reinterpret_cast<uint32_t*>(&h2);
        }
    }
}

// ---------------- kernel 3: HMMA GEMM  D[o, px] = Whalf x Cols^T ---------------
// grid (2, 64): x = o tile (128 o), y = px tile (256 px). 1 wave (128 CTAs).
// warp tile 64(m) x 64(n): warps laid out 2(m) x 4(n). K = 2304, fp16 1-pass.
__global__ void __launch_bounds__(256, 1)
gemm_kernel(const float* __restrict__ bias, float* __restrict__ out) {
    extern __shared__ __align__(16) char dyn_smem[];
    const uint32_t smem_base = smem_u32(dyn_smem);
    const uint32_t tile0 = (smem_base + 1023u) & ~1023u;   // 1024-aligned stages

    const int tid  = threadIdx.x;
    const int wid  = tid >> 5;
    const int lane = tid & 31;
    const int o_tile = blockIdx.x;            // 0..1
    const int pxb    = blockIdx.y << 8;       // 256 px per CTA

    const int wm = wid & 1;                   // m offset 64*wm
    const int wn = wid >> 1;                  // n offset 64*wn

    const __half* wA = g_whalf + (size_t)o_tile * 128 * CK;
    const __half* cB = g_cols + (size_t)pxb * CK;

    const int r0 = tid >> 3;
    const int sg = tid & 7;

    auto load_chunk = [&](int j) {
        int st = j % STG;
        uint32_t sa = tile0 + st * STAGE_BYTES;
        uint32_t sb = sa + 16384;
        int koff = j * KC + sg * 8;
        #pragma unroll
        for (int q = 0; q < 4; ++q) {        // A: 128 rows
            int r = r0 + (q << 5);
            cp16(sa + sw128((uint32_t)(r * 128 + sg * 16)), wA + (size_t)r * CK + koff);
        }
        #pragma unroll
        for (int q = 0; q < 8; ++q) {        // B: 256 rows
            int r = r0 + (q << 5);
            cp16(sb + sw128((uint32_t)(r * 128 + sg * 16)), cB + (size_t)r * CK + koff);
        }
        CP_COMMIT();
    };

    float acc[4][8][4];
    #pragma unroll
    for (int i = 0; i < 4; ++i)
        #pragma unroll
        for (int j = 0; j < 8; ++j)
            #pragma unroll
            for (int q = 0; q < 4; ++q) acc[i][j][q] = 0.0f;

    const uint32_t aRow = (uint32_t)(wm * 64 + (lane & 15));
    const uint32_t aCb  = (uint32_t)((lane >> 4) << 4);
    const uint32_t bRow = (uint32_t)(wn * 64 + ((lane >> 4) << 3) + (lane & 7));
    const uint32_t bCb  = (uint32_t)(((lane >> 3) & 1) << 4);

    load_chunk(0);
    load_chunk(1);
    load_chunk(2);

    for (int i = 0; i < NCHUNK; ++i) {
        CP_WAIT2();
        __syncthreads();
        if (i + STG - 1 < NCHUNK) load_chunk(i + STG - 1);

        int st = i % STG;
        uint32_t sa = tile0 + st * STAGE_BYTES;
        uint32_t sb = sa + 16384;

        #pragma unroll
        for (int kk = 0; kk < 4; ++kk) {
            uint32_t a[4][4], b[8][2];
            #pragma unroll
            for (int mf = 0; mf < 4; ++mf)
                ldsm_x4(a[mf], sa + sw128((aRow + mf * 16) * 128 + aCb + kk * 32));
            #pragma unroll
            for (int half = 0; half < 4; ++half) {
                uint32_t r[4];
                ldsm_x4(r, sb + sw128((bRow + half * 16) * 128 + bCb + kk * 32));
                b[2 * half][0] = r[0]; b[2 * half][1] = r[1];
                b[2 * half + 1][0] = r[2]; b[2 * half + 1][1] = r[3];
            }
            #pragma unroll
            for (int mf = 0; mf < 4; ++mf)
                #pragma unroll
                for (int nf = 0; nf < 8; ++nf)
                    mma16816(acc[mf][nf], a[mf], b[nf]);
        }
    }
    CP_WAIT0();

    // ---- epilogue: direct register -> gmem stores -----------------------------
    const int bb  = pxb >> 12;
    const int hw0 = pxb & 4095;
    const int oBase = o_tile * 128 + wm * 64 + (lane >> 2);
    const int nBase = hw0 + wn * 64 + (lane & 3) * 2;

    #pragma unroll
    for (int mf = 0; mf < 4; ++mf) {
        int o0 = oBase + mf * 16;
        float bz0 = __ldg(bias + o0);
        float bz8 = __ldg(bias + o0 + 8);
        float* op0 = out + (bb << 20) + (o0 << 12) + nBase;
        float* op8 = op0 + (8 << 12);
        #pragma unroll
        for (int nf = 0; nf < 8; ++nf) {
            float2 v0 = make_float2(acc[mf][nf][0] + bz0, acc[mf][nf][1] + bz0);
            float2 v1 = make_float2(acc[mf][nf][2] + bz8, acc[mf][nf][3] + bz8);
            *reinterpret_cast<float2*>(op0 + nf * 8) = v0;
            *reinterpret_cast<float2*>(op8 + nf * 8) = v1;
        }
    }
}

// ---------------- launch ------------------------------------------------------
extern "C" void kernel_launch(void* const* d_in, const int* in_sizes, int n_in,
                              void* d_out, int out_size) {
    const float* x      = (const float*)d_in[0];   // (4,256,64,64)
    const float* w_om   = (const float*)d_in[1];   // (27,256,3,3)
    const float* b_om   = (const float*)d_in[2];   // (27,)
    const float* weight = (const float*)d_in[3];   // (256,256,3,3)
    const float* bias   = (const float*)d_in[4];   // (256,)
    float* out = (float*)d_out;                    // (4,256,64,64)

    cudaFuncSetAttribute(gemm_kernel, cudaFuncAttributeMaxDynamicSharedMemorySize, SMEM_DYN);

    prep_all_kernel<<<4928, 256>>>(x, w_om, weight);
    gather_kernel<<<2048, 256>>>(b_om);
    gemm_kernel<<<dim3(2, 64), 256, SMEM_DYN>>>(bias, out);
}

// round 11
// speedup vs baseline: 10.2037x; 1.3214x over previous
#include <cuda_runtime.h>
#include <cuda_bf16.h>
#include <cuda_fp16.h>
#include <math.h>
#include <cstdint>

// Problem constants
#define B   4
#define C   256
#define H   64
#define W   64
#define O   256
#define K   9           // 3x3
#define HW  4096        // H*W
#define CK  2304        // C*K
#define NPIX 16384      // B*H*W

// main GEMM config (1-pass fp16)
#define KC      64
#define NCHUNK  36      // 2304/64
#define STG     4
#define STAGE_BYTES 49152   // A 16KB + B 32KB
#define SMEM_DYN (1024 + STG * STAGE_BYTES)

// offset-conv GEMM config
#define NCH2    36      // 9 taps x 4 chunks of 64ch
#define STG2    4
#define STAGE2  20480   // A 4KB + B 16KB
#define SMEM2   (1024 + STG2 * STAGE2)

// ---------------- scratch (__device__ globals; no allocs allowed) -------------
__device__ float  g_om[B * 27 * HW];              // offset-conv output
__device__ float  g_xhwc[(size_t)NPIX * C];       // x in NHWC fp32 (for gather)
__device__ __half g_xhalf[(size_t)NPIX * C];      // x in NHWC fp16 (for offconv B)
__device__ __half g_womh[32 * CK];                // w_om k-major fp16, rows 27..31 = 0
__device__ __half g_whalf[O * CK];                // weight k-major fp16
__device__ __half g_cols[(size_t)NPIX * CK];      // im2col cols fp16
__device__ __half g_zero[64];                     // zero-initialized OOB source

// ---------------- PTX helpers -------------------------------------------------
__device__ __forceinline__ uint32_t smem_u32(const void* p) {
    uint32_t a;
    asm("{ .reg .u64 t; cvta.to.shared.u64 t, %1; cvt.u32.u64 %0, t; }" : "=r"(a) : "l"(p));
    return a;
}
__device__ __forceinline__ void cp16(uint32_t dst, const void* src) {
    asm volatile("cp.async.cg.shared.global [%0], [%1], 16;" :: "r"(dst), "l"(src) : "memory");
}
#define CP_COMMIT() asm volatile("cp.async.commit_group;" ::: "memory")
#define CP_WAIT2()  asm volatile("cp.async.wait_group 2;" ::: "memory")
#define CP_WAIT0()  asm volatile("cp.async.wait_group 0;" ::: "memory")

__device__ __forceinline__ uint32_t sw128(uint32_t off) { return off ^ ((off >> 3) & 0x70); }

__device__ __forceinline__ void ldsm_x4(uint32_t* r, uint32_t addr) {
    asm volatile("ldmatrix.sync.aligned.m8n8.x4.shared.b16 {%0,%1,%2,%3}, [%4];"
        : "=r"(r[0]), "=r"(r[1]), "=r"(r[2]), "=r"(r[3]) : "r"(addr));
}
__device__ __forceinline__ void mma16816(float* d, const uint32_t* a, const uint32_t* b) {
    asm volatile("mma.sync.aligned.m16n8k16.row.col.f32.f16.f16.f32 "
        "{%0,%1,%2,%3}, {%4,%5,%6,%7}, {%8,%9}, {%0,%1,%2,%3};"
        : "+f"(d[0]), "+f"(d[1]), "+f"(d[2]), "+f"(d[3])
        : "r"(a[0]), "r"(a[1]), "r"(a[2]), "r"(a[3]), "r"(b[0]), "r"(b[1]));
}

// ---------------- kernel 1: prep (transpose x2 + wsplit + womprep) -------------
// grid 4960 x 256 threads:
//   [0, 4096)    : NCHW->NHWC transpose (fp32 + fp16 copies)
//   [4096, 4672) : wsplit -> fp16 k-major
//   [4672, 4960) : w_om -> fp16 k-major padded to 32 rows
__global__ void __launch_bounds__(256) prep_kernel(const float* __restrict__ x,
                                                   const float* __restrict__ w_om,
                                                   const float* __restrict__ weight) {
    const int bid = blockIdx.x;
    const int tid = threadIdx.x;

    if (bid < 4096) {
        __shared__ float t[32][33];
        const int hw0 = (bid & 127) << 5;
        const int c0  = ((bid >> 7) & 7) << 5;
        const int b   = bid >> 10;
        const int tx = tid & 31, ty = tid >> 5;
        #pragma unroll
        for (int j = 0; j < 4; ++j) {
            int c = c0 + ty + 8 * j;
            t[ty + 8 * j][tx] = x[(((b << 8) + c) << 12) + hw0 + tx];
        }
        __syncthreads();
        #pragma unroll
        for (int j = 0; j < 4; ++j) {
            int hw = hw0 + ty + 8 * j;
            float v = t[tx][ty + 8 * j];
            size_t idx = (size_t)(((b << 12) + hw) << 8) + c0 + tx;
            g_xhwc[idx]  = v;
            g_xhalf[idx] = __float2half_rn(v);
        }
    } else if (bid < 4672) {
        // ---- wsplit: fp16, k-major ----
        int i = (bid - 4096) * 1024 + tid * 4;  // < 589824
        const float4 v4 = *reinterpret_cast<const float4*>(weight + i);
        const float vs[4] = { v4.x, v4.y, v4.z, v4.w };
        #pragma unroll
        for (int q = 0; q < 4; ++q) {
            int e = i + q;
            int o = e / CK, r = e - o * CK;
            int c = r / 9, k = r - c * 9;
            g_whalf[o * CK + k * 256 + c] = __float2half_rn(vs[q]);
        }
    } else {
        // ---- womprep: womh[o][k*256+c] = w_om[o*2304 + c*9 + k], o<27 else 0 ----
        int i = (bid - 4672) * 256 + tid;       // < 73728 exactly
        int o = i / CK, r = i - o * CK;
        int k = r >> 8, c = r & 255;
        g_womh[i] = (o < 27) ? __float2half_rn(w_om[o * CK + c * 9 + k]) : __half(0.0f);
    }
}

// ---------------- kernel 2: offset-conv HMMA GEMM ------------------------------
// om[27, px] = w_om[27 x 2304] x im2col(x)[2304 x px].  B rows built on the fly
// from fp16 NHWC x: tap row = contiguous 64-ch chunk at shifted pixel (or zeros).
// grid 128 (one 128-px tile each), 256 threads (8 warps); warp tile 32(m) x 16(n).
__global__ void __launch_bounds__(256, 1)
offconv_kernel() {
    extern __shared__ __align__(16) char dyn_smem[];
    __shared__ int spx[K][128];                    // per-(tap, px) element offset or -1

    const uint32_t smem_base = smem_u32(dyn_smem);
    const uint32_t tile0 = (smem_base + 1023u) & ~1023u;

    const int tid  = threadIdx.x;
    const int wid  = tid >> 5;
    const int lane = tid & 31;
    const int pxb  = blockIdx.x << 7;              // 128 px per CTA
    const int b    = pxb >> 12;
    const int hwb  = pxb & 4095;

    // precompute per-px per-tap source offsets
    for (int i = tid; i < K * 128; i += 256) {
        int k = i >> 7, p = i & 127;
        int hw = hwb + p;
        int h = hw >> 6, w = hw & 63;
        int ky = k / 3 - 1, kx = k - (ky + 1) * 3 - 1;
        bool valid = ((unsigned)(h + ky) < H) && ((unsigned)(w + kx) < W);
        spx[k][p] = valid ? (((b << 12) + hw + ky * 64 + kx) << 8) : -1;
    }
    __syncthreads();

    const int rA = tid >> 3;      // 0..31
    const int sg = tid & 7;

    auto load_chunk = [&](int j) {
        int st = j % STG2;
        uint32_t sa = tile0 + st * STAGE2;         // A: 32 x 128B = 4KB
        uint32_t sb = sa + 4096;                   // B: 128 x 128B = 16KB
        int k  = j >> 2;
        int c0 = (j & 3) << 6;
        cp16(sa + sw128((uint32_t)(rA * 128 + sg * 16)), g_womh + rA * CK + k * 256 + c0 + sg * 8);
        #pragma unroll
        for (int q = 0; q < 4; ++q) {
            int idx = tid + (q << 8);
            int row = idx >> 3, s2 = idx & 7;
            int off = spx[k][row];
            const __half* src = (off >= 0) ? (g_xhalf + off + c0 + s2 * 8) : (g_zero + s2 * 8);
            cp16(sb + sw128((uint32_t)(row * 128 + s2 * 16)), src);
        }
        CP_COMMIT();
    };

    float acc[2][2][4];
    #pragma unroll
    for (int i = 0; i < 2; ++i)
        #pragma unroll
        for (int j = 0; j < 2; ++j)
            #pragma unroll
            for (int q = 0; q < 4; ++q) acc[i][j][q] = 0.0f;

    const uint32_t aRow = (uint32_t)(lane & 15);
    const uint32_t aCb  = (uint32_t)((lane >> 4) << 4);
    const uint32_t bRow = (uint32_t)(wid * 16 + ((lane >> 4) << 3) + (lane & 7));
    const uint32_t bCb  = (uint32_t)(((lane >> 3) & 1) << 4);

    load_chunk(0);
    load_chunk(1);
    load_chunk(2);

    for (int i = 0; i < NCH2; ++i) {
        CP_WAIT2();
        __syncthreads();
        if (i + STG2 - 1 < NCH2) load_chunk(i + STG2 - 1);

        int st = i % STG2;
        uint32_t sa = tile0 + st * STAGE2;
        uint32_t sb = sa + 4096;

        #pragma unroll
        for (int kk = 0; kk < 4; ++kk) {
            uint32_t a[2][4], bfr[2][2];
            #pragma unroll
            for (int mf = 0; mf < 2; ++mf)
                ldsm_x4(a[mf], sa + sw128((aRow + mf * 16) * 128 + aCb + kk * 32));
            {
                uint32_t r[4];
                ldsm_x4(r, sb + sw128(bRow * 128 + bCb + kk * 32));
                bfr[0][0] = r[0]; bfr[0][1] = r[1];
                bfr[1][0] = r[2]; bfr[1][1] = r[3];
            }
            #pragma unroll
            for (int mf = 0; mf < 2; ++mf)
                #pragma unroll
                for (int nf = 0; nf < 2; ++nf)
                    mma16816(acc[mf][nf], a[mf], bfr[nf]);
        }
    }
    CP_WAIT0();

    // epilogue: D[m=o][n=px] -> g_om[b][o][hw]
    const int nBase = hwb + wid * 16 + (lane & 3) * 2;
    #pragma unroll
    for (int mf = 0; mf < 2; ++mf) {
        int o0 = mf * 16 + (lane >> 2);
        int o8 = o0 + 8;
        #pragma unroll
        for (int nf = 0; nf < 2; ++nf) {
            int n = nBase + nf * 8;
            if (o0 < 27)
                *reinterpret_cast<float2*>(g_om + (b * 27 + o0) * HW + n) =
                    make_float2(acc[mf][nf][0], acc[mf][nf][1]);
            if (o8 < 27)
                *reinterpret_cast<float2*>(g_om + (b * 27 + o8) * HW + n) =
                    make_float2(acc[mf][nf][2], acc[mf][nf][3]);
        }
    }
}

// ---------------- kernel 3: fused params + gather (fp16 cols) ------------------
// grid 2048, block 256 = 8 px. Phase 1: 72 threads compute the 8x9 sampling
// params into smem. Phase 2: warp = one pixel, lane = 2 channels (float2/half2).
__global__ void __launch_bounds__(256) gather_kernel(const float* __restrict__ b_om) {
    __shared__ float4 s_ww[8][9];
    __shared__ int4   s_cc[8][9];

    const int tid  = threadIdx.x;
    const int pix0 = blockIdx.x << 3;
    const int b    = pix0 >> 12;

    if (tid < 72) {
        const int p = tid / 9;
        const int k = tid - p * 9;
        const int hw = (pix0 + p) & 4095;
        const int h  = hw >> 6;
        const int w  = hw & 63;
        const float* omb = g_om + b * 27 * HW + hw;

        float off_y = omb[(2 * k    ) * HW] + b_om[2 * k];
        float off_x = omb[(2 * k + 1) * HW] + b_om[2 * k + 1];
        float mval  = omb[(18 + k   ) * HW] + b_om[18 + k];
        float m = 1.0f / (1.0f + expf(-mval));

        float py = (float)(h - 1 + k / 3) + off_y;
        float px = (float)(w - 1 + k % 3) + off_x;

        float y0f = floorf(py), x0f = floorf(px);
        float ly = py - y0f, lx = px - x0f;
        int y0 = (int)y0f, x0 = (int)x0f;
        int y1 = y0 + 1,   x1 = x0 + 1;

        float vy0 = (y0 >= 0 && y0 < H) ? 1.0f : 0.0f;
        float vy1 = (y1 >= 0 && y1 < H) ? 1.0f : 0.0f;
        float vx0 = (x0 >= 0 && x0 < W) ? 1.0f : 0.0f;
        float vx1 = (x1 >= 0 && x1 < W) ? 1.0f : 0.0f;

        float4 wv;
        wv.x = (1.0f - ly) * (1.0f - lx) * m * vy0 * vx0;
        wv.y = (1.0f - ly) * lx          * m * vy0 * vx1;
        wv.z = ly * (1.0f - lx)          * m * vy1 * vx0;
        wv.w = ly * lx                   * m * vy1 * vx1;

        int4 cv;
        cv.x = min(max(y0, 0), H - 1) * W;
        cv.y = min(max(y1, 0), H - 1) * W;
        cv.z = min(max(x0, 0), W - 1);
        cv.w = min(max(x1, 0), W - 1);

        s_ww[p][k] = wv;
        s_cc[p][k] = cv;
    }
    __syncthreads();

    const int wid  = tid >> 5;
    const int lane = tid & 31;
    const int px   = pix0 + wid;

    const float2* xb2 = reinterpret_cast<const float2*>(g_xhwc + ((size_t)b << 20));
    uint32_t* outp = reinterpret_cast<uint32_t*>(g_cols + (size_t)px * CK);

    #pragma unroll
    for (int k = 0; k < K; ++k) {
        const float4 ww = s_ww[wid][k];
        const int4   cc = s_cc[wid][k];
        const int p00 = (cc.x + cc.z) << 7;
        const int p01 = (cc.x + cc.w) << 7;
        const int p10 = (cc.y + cc.z) << 7;
        const int p11 = (cc.y + cc.w) << 7;
        #pragma unroll
        for (int it = 0; it < 4; ++it) {
            const int c2 = (it << 5) + lane;
            float2 v00 = xb2[p00 + c2], v01 = xb2[p01 + c2];
            float2 v10 = xb2[p10 + c2], v11 = xb2[p11 + c2];
            float va = ww.x * v00.x + ww.y * v01.x + ww.z * v10.x + ww.w * v11.x;
            float vb = ww.x * v00.y + ww.y * v01.y + ww.z * v10.y + ww.w * v11.y;
            __half2 h2 = __floats2half2_rn(va, vb);
            outp[k * 128 + c2] = *reinterpret_cast<uint32_t*>(&h2);
        }
    }
}

// ---------------- kernel 4: HMMA GEMM  D[o, px] = Whalf x Cols^T ---------------
// grid (2, 64), 1 wave (128 CTAs); warp tile 64(m) x 64(n); K = 2304 fp16 1-pass.
__global__ void __launch_bounds__(256, 1)
gemm_kernel(const float* __restrict__ bias, float* __restrict__ out) {
    extern __shared__ __align__(16) char dyn_smem[];
    const uint32_t smem_base = smem_u32(dyn_smem);
    const uint32_t tile0 = (smem_base + 1023u) & ~1023u;

    const int tid  = threadIdx.x;
    const int wid  = tid >> 5;
    const int lane = tid & 31;
    const int o_tile = blockIdx.x;
    const int pxb    = blockIdx.y << 8;

    const int wm = wid & 1;
    const int wn = wid >> 1;

    const __half* wA = g_whalf + (size_t)o_tile * 128 * CK;
    const __half* cB = g_cols + (size_t)pxb * CK;

    const int r0 = tid >> 3;
    const int sg = tid & 7;

    auto load_chunk = [&](int j) {
        int st = j % STG;
        uint32_t sa = tile0 + st * STAGE_BYTES;
        uint32_t sb = sa + 16384;
        int koff = j * KC + sg * 8;
        #pragma unroll
        for (int q = 0; q < 4; ++q) {
            int r = r0 + (q << 5);
            cp16(sa + sw128((uint32_t)(r * 128 + sg * 16)), wA + (size_t)r * CK + koff);
        }
        #pragma unroll
        for (int q = 0; q < 8; ++q) {
            int r = r0 + (q << 5);
            cp16(sb + sw128((uint32_t)(r * 128 + sg * 16)), cB + (size_t)r * CK + koff);
        }
        CP_COMMIT();
    };

    float acc[4][8][4];
    #pragma unroll
    for (int i = 0; i < 4; ++i)
        #pragma unroll
        for (int j = 0; j < 8; ++j)
            #pragma unroll
            for (int q = 0; q < 4; ++q) acc[i][j][q] = 0.0f;

    const uint32_t aRow = (uint32_t)(wm * 64 + (lane & 15));
    const uint32_t aCb  = (uint32_t)((lane >> 4) << 4);
    const uint32_t bRow = (uint32_t)(wn * 64 + ((lane >> 4) << 3) + (lane & 7));
    const uint32_t bCb  = (uint32_t)(((lane >> 3) & 1) << 4);

    load_chunk(0);
    load_chunk(1);
    load_chunk(2);

    for (int i = 0; i < NCHUNK; ++i) {
        CP_WAIT2();
        __syncthreads();
        if (i + STG - 1 < NCHUNK) load_chunk(i + STG - 1);

        int st = i % STG;
        uint32_t sa = tile0 + st * STAGE_BYTES;
        uint32_t sb = sa + 16384;

        #pragma unroll
        for (int kk = 0; kk < 4; ++kk) {
            uint32_t a[4][4], b[8][2];
            #pragma unroll
            for (int mf = 0; mf < 4; ++mf)
                ldsm_x4(a[mf], sa + sw128((aRow + mf * 16) * 128 + aCb + kk * 32));
            #pragma unroll
            for (int half = 0; half < 4; ++half) {
                uint32_t r[4];
                ldsm_x4(r, sb + sw128((bRow + half * 16) * 128 + bCb + kk * 32));
                b[2 * half][0] = r[0]; b[2 * half][1] = r[1];
                b[2 * half + 1][0] = r[2]; b[2 * half + 1][1] = r[3];
            }
            #pragma unroll
            for (int mf = 0; mf < 4; ++mf)
                #pragma unroll
                for (int nf = 0; nf < 8; ++nf)
                    mma16816(acc[mf][nf], a[mf], b[nf]);
        }
    }
    CP_WAIT0();

    const int bb  = pxb >> 12;
    const int hw0 = pxb & 4095;
    const int oBase = o_tile * 128 + wm * 64 + (lane >> 2);
    const int nBase = hw0 + wn * 64 + (lane & 3) * 2;

    #pragma unroll
    for (int mf = 0; mf < 4; ++mf) {
        int o0 = oBase + mf * 16;
        float bz0 = __ldg(bias + o0);
        float bz8 = __ldg(bias + o0 + 8);
        float* op0 = out + (bb << 20) + (o0 << 12) + nBase;
        float* op8 = op0 + (8 << 12);
        #pragma unroll
        for (int nf = 0; nf < 8; ++nf) {
            float2 v0 = make_float2(acc[mf][nf][0] + bz0, acc[mf][nf][1] + bz0);
            float2 v1 = make_float2(acc[mf][nf][2] + bz8, acc[mf][nf][3] + bz8);
            *reinterpret_cast<float2*>(op0 + nf * 8) = v0;
            *reinterpret_cast<float2*>(op8 + nf * 8) = v1;
        }
    }
}

// ---------------- launch ------------------------------------------------------
extern "C" void kernel_launch(void* const* d_in, const int* in_sizes, int n_in,
                              void* d_out, int out_size) {
    const float* x      = (const float*)d_in[0];   // (4,256,64,64)
    const float* w_om   = (const float*)d_in[1];   // (27,256,3,3)
    const float* b_om   = (const float*)d_in[2];   // (27,)
    const float* weight = (const float*)d_in[3];   // (256,256,3,3)
    const float* bias   = (const float*)d_in[4];   // (256,)
    float* out = (float*)d_out;                    // (4,256,64,64)

    cudaFuncSetAttribute(offconv_kernel, cudaFuncAttributeMaxDynamicSharedMemorySize, SMEM2);
    cudaFuncSetAttribute(gemm_kernel, cudaFuncAttributeMaxDynamicSharedMemorySize, SMEM_DYN);

    prep_kernel<<<4960, 256>>>(x, w_om, weight);
    offconv_kernel<<<128, 256, SMEM2>>>();
    gather_kernel<<<2048, 256>>>(b_om);
    gemm_kernel<<<dim3(2, 64), 256, SMEM_DYN>>>(bias, out);
}

// round 12
// speedup vs baseline: 10.8849x; 1.0668x over previous
#include <cuda_runtime.h>
#include <cuda_bf16.h>
#include <cuda_fp16.h>
#include <math.h>
#include <cstdint>

// Problem constants
#define B   4
#define C   256
#define H   64
#define W   64
#define O   256
#define K   9           // 3x3
#define HW  4096        // H*W
#define CK  2304        // C*K
#define NPIX 16384      // B*H*W

// main GEMM config (1-pass fp16, occ 2)
#define KC      64
#define NCHUNK  36      // 2304/64
#define STG     3
#define STAGE_BYTES 32768   // A 16KB + B 16KB
#define SMEM_DYN (1024 + STG * STAGE_BYTES)

// offset-conv GEMM config
#define NCH2    36      // 9 taps x 4 chunks of 64ch
#define STG2    4
#define STAGE2  20480   // A 4KB + B 16KB
#define SMEM2   (1024 + STG2 * STAGE2)

// ---------------- scratch (__device__ globals; no allocs allowed) -------------
__device__ float  g_om[B * 27 * HW];              // offset-conv output
__device__ float  g_xhwc[(size_t)NPIX * C];       // x in NHWC fp32 (for gather)
__device__ __half g_xhalf[(size_t)NPIX * C];      // x in NHWC fp16 (for offconv B)
__device__ __half g_womh[32 * CK];                // w_om k-major fp16, rows 27..31 = 0
__device__ __half g_whalf[O * CK];                // weight k-major fp16
__device__ __half g_cols[(size_t)NPIX * CK];      // im2col cols fp16
__device__ __half g_zero[64];                     // zero-initialized OOB source

// ---------------- PTX helpers -------------------------------------------------
__device__ __forceinline__ uint32_t smem_u32(const void* p) {
    uint32_t a;
    asm("{ .reg .u64 t; cvta.to.shared.u64 t, %1; cvt.u32.u64 %0, t; }" : "=r"(a) : "l"(p));
    return a;
}
__device__ __forceinline__ void cp16(uint32_t dst, const void* src) {
    asm volatile("cp.async.cg.shared.global [%0], [%1], 16;" :: "r"(dst), "l"(src) : "memory");
}
#define CP_COMMIT() asm volatile("cp.async.commit_group;" ::: "memory")
#define CP_WAIT1()  asm volatile("cp.async.wait_group 1;" ::: "memory")
#define CP_WAIT2()  asm volatile("cp.async.wait_group 2;" ::: "memory")
#define CP_WAIT0()  asm volatile("cp.async.wait_group 0;" ::: "memory")

__device__ __forceinline__ uint32_t sw128(uint32_t off) { return off ^ ((off >> 3) & 0x70); }

__device__ __forceinline__ void ldsm_x4(uint32_t* r, uint32_t addr) {
    asm volatile("ldmatrix.sync.aligned.m8n8.x4.shared.b16 {%0,%1,%2,%3}, [%4];"
        : "=r"(r[0]), "=r"(r[1]), "=r"(r[2]), "=r"(r[3]) : "r"(addr));
}
__device__ __forceinline__ void mma16816(float* d, const uint32_t* a, const uint32_t* b) {
    asm volatile("mma.sync.aligned.m16n8k16.row.col.f32.f16.f16.f32 "
        "{%0,%1,%2,%3}, {%4,%5,%6,%7}, {%8,%9}, {%0,%1,%2,%3};"
        : "+f"(d[0]), "+f"(d[1]), "+f"(d[2]), "+f"(d[3])
        : "r"(a[0]), "r"(a[1]), "r"(a[2]), "r"(a[3]), "r"(b[0]), "r"(b[1]));
}

// ---------------- kernel 1: prep (transpose x2 + wsplit + womprep) -------------
// grid 4960 x 256 threads:
//   [0, 4096)    : NCHW->NHWC transpose (fp32 + fp16 copies)
//   [4096, 4672) : wsplit -> fp16 k-major
//   [4672, 4960) : w_om -> fp16 k-major padded to 32 rows
__global__ void __launch_bounds__(256) prep_kernel(const float* __restrict__ x,
                                                   const float* __restrict__ w_om,
                                                   const float* __restrict__ weight) {
    const int bid = blockIdx.x;
    const int tid = threadIdx.x;

    if (bid < 4096) {
        __shared__ float t[32][33];
        const int hw0 = (bid & 127) << 5;
        const int c0  = ((bid >> 7) & 7) << 5;
        const int b   = bid >> 10;
        const int tx = tid & 31, ty = tid >> 5;
        #pragma unroll
        for (int j = 0; j < 4; ++j) {
            int c = c0 + ty + 8 * j;
            t[ty + 8 * j][tx] = x[(((b << 8) + c) << 12) + hw0 + tx];
        }
        __syncthreads();
        #pragma unroll
        for (int j = 0; j < 4; ++j) {
            int hw = hw0 + ty + 8 * j;
            float v = t[tx][ty + 8 * j];
            size_t idx = (size_t)(((b << 12) + hw) << 8) + c0 + tx;
            g_xhwc[idx]  = v;
            g_xhalf[idx] = __float2half_rn(v);
        }
    } else if (bid < 4672) {
        // ---- wsplit: fp16, k-major ----
        int i = (bid - 4096) * 1024 + tid * 4;  // < 589824
        const float4 v4 = *reinterpret_cast<const float4*>(weight + i);
        const float vs[4] = { v4.x, v4.y, v4.z, v4.w };
        #pragma unroll
        for (int q = 0; q < 4; ++q) {
            int e = i + q;
            int o = e / CK, r = e - o * CK;
            int c = r / 9, k = r - c * 9;
            g_whalf[o * CK + k * 256 + c] = __float2half_rn(vs[q]);
        }
    } else {
        // ---- womprep: womh[o][k*256+c] = w_om[o*2304 + c*9 + k], o<27 else 0 ----
        int i = (bid - 4672) * 256 + tid;       // < 73728 exactly
        int o = i / CK, r = i - o * CK;
        int k = r >> 8, c = r & 255;
        g_womh[i] = (o < 27) ? __float2half_rn(w_om[o * CK + c * 9 + k]) : __half(0.0f);
    }
}

// ---------------- kernel 2: offset-conv HMMA GEMM ------------------------------
// om[27, px] = w_om[27 x 2304] x im2col(x)[2304 x px].  B rows built on the fly
// from fp16 NHWC x: tap row = contiguous 64-ch chunk at shifted pixel (or zeros).
// grid 128 (one 128-px tile each), 256 threads (8 warps); warp tile 32(m) x 16(n).
__global__ void __launch_bounds__(256, 1)
offconv_kernel() {
    extern __shared__ __align__(16) char dyn_smem[];
    __shared__ int spx[K][128];                    // per-(tap, px) element offset or -1

    const uint32_t smem_base = smem_u32(dyn_smem);
    const uint32_t tile0 = (smem_base + 1023u) & ~1023u;

    const int tid  = threadIdx.x;
    const int wid  = tid >> 5;
    const int lane = tid & 31;
    const int pxb  = blockIdx.x << 7;              // 128 px per CTA
    const int b    = pxb >> 12;
    const int hwb  = pxb & 4095;

    // precompute per-px per-tap source offsets
    for (int i = tid; i < K * 128; i += 256) {
        int k = i >> 7, p = i & 127;
        int hw = hwb + p;
        int h = hw >> 6, w = hw & 63;
        int ky = k / 3 - 1, kx = k - (ky + 1) * 3 - 1;
        bool valid = ((unsigned)(h + ky) < H) && ((unsigned)(w + kx) < W);
        spx[k][p] = valid ? (((b << 12) + hw + ky * 64 + kx) << 8) : -1;
    }
    __syncthreads();

    const int rA = tid >> 3;      // 0..31
    const int sg = tid & 7;

    auto load_chunk = [&](int j) {
        int st = j % STG2;
        uint32_t sa = tile0 + st * STAGE2;         // A: 32 x 128B = 4KB
        uint32_t sb = sa + 4096;                   // B: 128 x 128B = 16KB
        int k  = j >> 2;
        int c0 = (j & 3) << 6;
        cp16(sa + sw128((uint32_t)(rA * 128 + sg * 16)), g_womh + rA * CK + k * 256 + c0 + sg * 8);
        #pragma unroll
        for (int q = 0; q < 4; ++q) {
            int idx = tid + (q << 8);
            int row = idx >> 3, s2 = idx & 7;
            int off = spx[k][row];
            const __half* src = (off >= 0) ? (g_xhalf + off + c0 + s2 * 8) : (g_zero + s2 * 8);
            cp16(sb + sw128((uint32_t)(row * 128 + s2 * 16)), src);
        }
        CP_COMMIT();
    };

    float acc[2][2][4];
    #pragma unroll
    for (int i = 0; i < 2; ++i)
        #pragma unroll
        for (int j = 0; j < 2; ++j)
            #pragma unroll
            for (int q = 0; q < 4; ++q) acc[i][j][q] = 0.0f;

    const uint32_t aRow = (uint32_t)(lane & 15);
    const uint32_t aCb  = (uint32_t)((lane >> 4) << 4);
    const uint32_t bRow = (uint32_t)(wid * 16 + ((lane >> 4) << 3) + (lane & 7));
    const uint32_t bCb  = (uint32_t)(((lane >> 3) & 1) << 4);

    load_chunk(0);
    load_chunk(1);
    load_chunk(2);

    for (int i = 0; i < NCH2; ++i) {
        CP_WAIT2();
        __syncthreads();
        if (i + STG2 - 1 < NCH2) load_chunk(i + STG2 - 1);

        int st = i % STG2;
        uint32_t sa = tile0 + st * STAGE2;
        uint32_t sb = sa + 4096;

        #pragma unroll
        for (int kk = 0; kk < 4; ++kk) {
            uint32_t a[2][4], bfr[2][2];
            #pragma unroll
            for (int mf = 0; mf < 2; ++mf)
                ldsm_x4(a[mf], sa + sw128((aRow + mf * 16) * 128 + aCb + kk * 32));
            {
                uint32_t r[4];
                ldsm_x4(r, sb + sw128(bRow * 128 + bCb + kk * 32));
                bfr[0][0] = r[0]; bfr[0][1] = r[1];
                bfr[1][0] = r[2]; bfr[1][1] = r[3];
            }
            #pragma unroll
            for (int mf = 0; mf < 2; ++mf)
                #pragma unroll
                for (int nf = 0; nf < 2; ++nf)
                    mma16816(acc[mf][nf], a[mf], bfr[nf]);
        }
    }
    CP_WAIT0();

    // epilogue: D[m=o][n=px] -> g_om[b][o][hw]
    const int nBase = hwb + wid * 16 + (lane & 3) * 2;
    #pragma unroll
    for (int mf = 0; mf < 2; ++mf) {
        int o0 = mf * 16 + (lane >> 2);
        int o8 = o0 + 8;
        #pragma unroll
        for (int nf = 0; nf < 2; ++nf) {
            int n = nBase + nf * 8;
            if (o0 < 27)
                *reinterpret_cast<float2*>(g_om + (b * 27 + o0) * HW + n) =
                    make_float2(acc[mf][nf][0], acc[mf][nf][1]);
            if (o8 < 27)
                *reinterpret_cast<float2*>(g_om + (b * 27 + o8) * HW + n) =
                    make_float2(acc[mf][nf][2], acc[mf][nf][3]);
        }
    }
}

// ---------------- kernel 3: fused params + gather (float4 path) ----------------
// grid 2048, block 256 = 8 px. Phase 1: 72 threads compute the 8x9 sampling
// params into smem. Phase 2: warp = one pixel, lane = 4 channels (float4/uint2).
__global__ void __launch_bounds__(256) gather_kernel(const float* __restrict__ b_om) {
    __shared__ float4 s_ww[8][9];
    __shared__ int4   s_cc[8][9];

    const int tid  = threadIdx.x;
    const int pix0 = blockIdx.x << 3;
    const int b    = pix0 >> 12;

    if (tid < 72) {
        const int p = tid / 9;
        const int k = tid - p * 9;
        const int hw = (pix0 + p) & 4095;
        const int h  = hw >> 6;
        const int w  = hw & 63;
        const float* omb = g_om + b * 27 * HW + hw;

        float off_y = omb[(2 * k    ) * HW] + b_om[2 * k];
        float off_x = omb[(2 * k + 1) * HW] + b_om[2 * k + 1];
        float mval  = omb[(18 + k   ) * HW] + b_om[18 + k];
        float m = 1.0f / (1.0f + expf(-mval));

        float py = (float)(h - 1 + k / 3) + off_y;
        float px = (float)(w - 1 + k % 3) + off_x;

        float y0f = floorf(py), x0f = floorf(px);
        float ly = py - y0f, lx = px - x0f;
        int y0 = (int)y0f, x0 = (int)x0f;
        int y1 = y0 + 1,   x1 = x0 + 1;

        float vy0 = (y0 >= 0 && y0 < H) ? 1.0f : 0.0f;
        float vy1 = (y1 >= 0 && y1 < H) ? 1.0f : 0.0f;
        float vx0 = (x0 >= 0 && x0 < W) ? 1.0f : 0.0f;
        float vx1 = (x1 >= 0 && x1 < W) ? 1.0f : 0.0f;

        float4 wv;
        wv.x = (1.0f - ly) * (1.0f - lx) * m * vy0 * vx0;
        wv.y = (1.0f - ly) * lx          * m * vy0 * vx1;
        wv.z = ly * (1.0f - lx)          * m * vy1 * vx0;
        wv.w = ly * lx                   * m * vy1 * vx1;

        int4 cv;
        cv.x = min(max(y0, 0), H - 1) * W;
        cv.y = min(max(y1, 0), H - 1) * W;
        cv.z = min(max(x0, 0), W - 1);
        cv.w = min(max(x1, 0), W - 1);

        s_ww[p][k] = wv;
        s_cc[p][k] = cv;
    }
    __syncthreads();

    const int wid  = tid >> 5;
    const int lane = tid & 31;
    const int px   = pix0 + wid;

    const float4* xb4 = reinterpret_cast<const float4*>(g_xhwc + ((size_t)b << 20));
    uint2* outp = reinterpret_cast<uint2*>(g_cols + (size_t)px * CK);

    #pragma unroll
    for (int k = 0; k < K; ++k) {
        const float4 ww = s_ww[wid][k];
        const int4   cc = s_cc[wid][k];
        const int p00 = (cc.x + cc.z) << 6;   // float4 units (64 per px)
        const int p01 = (cc.x + cc.w) << 6;
        const int p10 = (cc.y + cc.z) << 6;
        const int p11 = (cc.y + cc.w) << 6;
        #pragma unroll
        for (int it = 0; it < 2; ++it) {
            const int c4 = (it << 5) + lane;   // float4 index: channels 4*c4..4*c4+3
            float4 v00 = xb4[p00 + c4], v01 = xb4[p01 + c4];
            float4 v10 = xb4[p10 + c4], v11 = xb4[p11 + c4];
            float va = ww.x * v00.x + ww.y * v01.x + ww.z * v10.x + ww.w * v11.x;
            float vb = ww.x * v00.y + ww.y * v01.y + ww.z * v10.y + ww.w * v11.y;
            float vc = ww.x * v00.z + ww.y * v01.z + ww.z * v10.z + ww.w * v11.z;
            float vd = ww.x * v00.w + ww.y * v01.w + ww.z * v10.w + ww.w * v11.w;
            __half2 h2a = __floats2half2_rn(va, vb);
            __half2 h2b = __floats2half2_rn(vc, vd);
            uint2 st;
            st.x = *reinterpret_cast<uint32_t*>(&h2a);
            st.y = *reinterpret_cast<uint32_t*>(&h2b);
            outp[k * 64 + c4] = st;
        }
    }
}

// ---------------- kernel 4: HMMA GEMM  D[o, px] = Whalf x Cols^T ---------------
// grid (2, 128): tile 128(o) x 128(px), 256 CTAs, occupancy 2 -> single wave.
// 8 warps as 2(m) x 4(n); warp tile 64 x 32. 3-stage cp.async, K = 2304 fp16.
__global__ void __launch_bounds__(256, 2)
gemm_kernel(const float* __restrict__ bias, float* __restrict__ out) {
    extern __shared__ __align__(16) char dyn_smem[];
    const uint32_t smem_base = smem_u32(dyn_smem);
    const uint32_t tile0 = (smem_base + 1023u) & ~1023u;

    const int tid  = threadIdx.x;
    const int wid  = tid >> 5;
    const int lane = tid & 31;
    const int o_tile = blockIdx.x;            // 0..1 (fast dim: same-px pair adjacent)
    const int pxb    = blockIdx.y << 7;       // 128 px per CTA

    const int wm = wid & 1;                   // m offset 64*wm
    const int wn = wid >> 1;                  // n offset 32*wn

    const __half* wA = g_whalf + (size_t)o_tile * 128 * CK;
    const __half* cB = g_cols + (size_t)pxb * CK;

    const int r0 = tid >> 3;                  // 0..31
    const int sg = tid & 7;

    auto load_chunk = [&](int j) {
        int st = j % STG;
        uint32_t sa = tile0 + st * STAGE_BYTES;
        uint32_t sb = sa + 16384;
        int koff = j * KC + sg * 8;
        #pragma unroll
        for (int q = 0; q < 4; ++q) {        // A: 128 rows
            int r = r0 + (q << 5);
            cp16(sa + sw128((uint32_t)(r * 128 + sg * 16)), wA + (size_t)r * CK + koff);
        }
        #pragma unroll
        for (int q = 0; q < 4; ++q) {        // B: 128 rows
            int r = r0 + (q << 5);
            cp16(sb + sw128((uint32_t)(r * 128 + sg * 16)), cB + (size_t)r * CK + koff);
        }
        CP_COMMIT();
    };

    float acc[4][4][4];
    #pragma unroll
    for (int i = 0; i < 4; ++i)
        #pragma unroll
        for (int j = 0; j < 4; ++j)
            #pragma unroll
            for (int q = 0; q < 4; ++q) acc[i][j][q] = 0.0f;

    const uint32_t aRow = (uint32_t)(wm * 64 + (lane & 15));
    const uint32_t aCb  = (uint32_t)((lane >> 4) << 4);
    const uint32_t bRow = (uint32_t)(wn * 32 + ((lane >> 4) << 3) + (lane & 7));
    const uint32_t bCb  = (uint32_t)(((lane >> 3) & 1) << 4);

    load_chunk(0);
    load_chunk(1);

    for (int i = 0; i < NCHUNK; ++i) {
        if (i + 1 < NCHUNK) CP_WAIT1(); else CP_WAIT0();
        __syncthreads();
        if (i + STG - 1 < NCHUNK) load_chunk(i + STG - 1);

        int st = i % STG;
        uint32_t sa = tile0 + st * STAGE_BYTES;
        uint32_t sb = sa + 16384;

        #pragma unroll
        for (int kk = 0; kk < 4; ++kk) {
            uint32_t a[4][4], b[4][2];
            #pragma unroll
            for (int mf = 0; mf < 4; ++mf)
                ldsm_x4(a[mf], sa + sw128((aRow + mf * 16) * 128 + aCb + kk * 32));
            #pragma unroll
            for (int half = 0; half < 2; ++half) {
                uint32_t r[4];
                ldsm_x4(r, sb + sw128((bRow + half * 16) * 128 + bCb + kk * 32));
                b[2 * half][0] = r[0]; b[2 * half][1] = r[1];
                b[2 * half + 1][0] = r[2]; b[2 * half + 1][1] = r[3];
            }
            #pragma unroll
            for (int mf = 0; mf < 4; ++mf)
                #pragma unroll
                for (int nf = 0; nf < 4; ++nf)
                    mma16816(acc[mf][nf], a[mf], b[nf]);
        }
    }
    CP_WAIT0();

    // ---- epilogue: direct register -> gmem stores -----------------------------
    const int bb  = pxb >> 12;
    const int hw0 = pxb & 4095;
    const int oBase = o_tile * 128 + wm * 64 + (lane >> 2);
    const int nBase = hw0 + wn * 32 + (lane & 3) * 2;

    #pragma unroll
    for (int mf = 0; mf < 4; ++mf) {
        int o0 = oBase + mf * 16;
        float bz0 = __ldg(bias + o0);
        float bz8 = __ldg(bias + o0 + 8);
        float* op0 = out + (bb << 20) + (o0 << 12) + nBase;
        float* op8 = op0 + (8 << 12);
        #pragma unroll
        for (int nf = 0; nf < 4; ++nf) {
            float2 v0 = make_float2(acc[mf][nf][0] + bz0, acc[mf][nf][1] + bz0);
            float2 v1 = make_float2(acc[mf][nf][2] + bz8, acc[mf][nf][3] + bz8);
            *reinterpret_cast<float2*>(op0 + nf * 8) = v0;
            *reinterpret_cast<float2*>(op8 + nf * 8) = v1;
        }
    }
}

// ---------------- launch ------------------------------------------------------
extern "C" void kernel_launch(void* const* d_in, const int* in_sizes, int n_in,
                              void* d_out, int out_size) {
    const float* x      = (const float*)d_in[0];   // (4,256,64,64)
    const float* w_om   = (const float*)d_in[1];   // (27,256,3,3)
    const float* b_om   = (const float*)d_in[2];   // (27,)
    const float* weight = (const float*)d_in[3];   // (256,256,3,3)
    const float* bias   = (const float*)d_in[4];   // (256,)
    float* out = (float*)d_out;                    // (4,256,64,64)

    cudaFuncSetAttribute(offconv_kernel, cudaFuncAttributeMaxDynamicSharedMemorySize, SMEM2);
    cudaFuncSetAttribute(gemm_kernel, cudaFuncAttributeMaxDynamicSharedMemorySize, SMEM_DYN);

    prep_kernel<<<4960, 256>>>(x, w_om, weight);
    offconv_kernel<<<128, 256, SMEM2>>>();
    gather_kernel<<<2048, 256>>>(b_om);
    gemm_kernel<<<dim3(2, 128), 256, SMEM_DYN>>>(bias, out);
}

// round 13
// speedup vs baseline: 11.7347x; 1.0781x over previous
#include <cuda_runtime.h>
#include <cuda_bf16.h>
#include <cuda_fp16.h>
#include <math.h>
#include <cstdint>

// Problem constants
#define B   4
#define C   256
#define H   64
#define W   64
#define O   256
#define K   9           // 3x3
#define HW  4096        // H*W
#define CK  2304        // C*K
#define NPIX 16384      // B*H*W

// main GEMM config (1-pass fp16, occ 2)
#define KC      64
#define NCHUNK  36      // 2304/64
#define STG     3
#define STAGE_BYTES 32768   // A 16KB + B 16KB
#define SMEM_DYN (1024 + STG * STAGE_BYTES)

// offset-conv GEMM config
#define NCH2    36      // 9 taps x 4 chunks of 64ch
#define STG2    4
#define STAGE2  20480   // A 4KB + B 16KB
#define SMEM2   (1024 + STG2 * STAGE2)

// ---------------- scratch (__device__ globals; no allocs allowed) -------------
__device__ float  g_om[B * 27 * HW];              // offset-conv output
__device__ __half g_xhalf[(size_t)NPIX * C];      // x in NHWC fp16 (offconv B + gather)
__device__ __half g_womh[32 * CK];                // w_om k-major fp16, rows 27..31 = 0
__device__ __half g_whalf[O * CK];                // weight k-major fp16
__device__ __half g_cols[(size_t)NPIX * CK];      // im2col cols fp16
__device__ __half g_zero[64];                     // zero-initialized OOB source

// ---------------- PTX helpers -------------------------------------------------
__device__ __forceinline__ uint32_t smem_u32(const void* p) {
    uint32_t a;
    asm("{ .reg .u64 t; cvta.to.shared.u64 t, %1; cvt.u32.u64 %0, t; }" : "=r"(a) : "l"(p));
    return a;
}
__device__ __forceinline__ void cp16(uint32_t dst, const void* src) {
    asm volatile("cp.async.cg.shared.global [%0], [%1], 16;" :: "r"(dst), "l"(src) : "memory");
}
#define CP_COMMIT() asm volatile("cp.async.commit_group;" ::: "memory")
#define CP_WAIT1()  asm volatile("cp.async.wait_group 1;" ::: "memory")
#define CP_WAIT2()  asm volatile("cp.async.wait_group 2;" ::: "memory")
#define CP_WAIT0()  asm volatile("cp.async.wait_group 0;" ::: "memory")

__device__ __forceinline__ uint32_t sw128(uint32_t off) { return off ^ ((off >> 3) & 0x70); }

__device__ __forceinline__ void ldsm_x4(uint32_t* r, uint32_t addr) {
    asm volatile("ldmatrix.sync.aligned.m8n8.x4.shared.b16 {%0,%1,%2,%3}, [%4];"
        : "=r"(r[0]), "=r"(r[1]), "=r"(r[2]), "=r"(r[3]) : "r"(addr));
}
__device__ __forceinline__ void mma16816(float* d, const uint32_t* a, const uint32_t* b) {
    asm volatile("mma.sync.aligned.m16n8k16.row.col.f32.f16.f16.f32 "
        "{%0,%1,%2,%3}, {%4,%5,%6,%7}, {%8,%9}, {%0,%1,%2,%3};"
        : "+f"(d[0]), "+f"(d[1]), "+f"(d[2]), "+f"(d[3])
        : "r"(a[0]), "r"(a[1]), "r"(a[2]), "r"(a[3]), "r"(b[0]), "r"(b[1]));
}

// ---------------- kernel 1: prep (transpose + wsplit + womprep) ----------------
// grid 4960 x 256 threads:
//   [0, 4096)    : NCHW->NHWC transpose (fp16 only)
//   [4096, 4672) : wsplit -> fp16 k-major
//   [4672, 4960) : w_om -> fp16 k-major padded to 32 rows
__global__ void __launch_bounds__(256) prep_kernel(const float* __restrict__ x,
                                                   const float* __restrict__ w_om,
                                                   const float* __restrict__ weight) {
    const int bid = blockIdx.x;
    const int tid = threadIdx.x;

    if (bid < 4096) {
        __shared__ float t[32][33];
        const int hw0 = (bid & 127) << 5;
        const int c0  = ((bid >> 7) & 7) << 5;
        const int b   = bid >> 10;
        const int tx = tid & 31, ty = tid >> 5;
        #pragma unroll
        for (int j = 0; j < 4; ++j) {
            int c = c0 + ty + 8 * j;
            t[ty + 8 * j][tx] = x[(((b << 8) + c) << 12) + hw0 + tx];
        }
        __syncthreads();
        #pragma unroll
        for (int j = 0; j < 4; ++j) {
            int hw = hw0 + ty + 8 * j;
            g_xhalf[(size_t)(((b << 12) + hw) << 8) + c0 + tx] =
                __float2half_rn(t[tx][ty + 8 * j]);
        }
    } else if (bid < 4672) {
        // ---- wsplit: fp16, k-major ----
        int i = (bid - 4096) * 1024 + tid * 4;  // < 589824
        const float4 v4 = *reinterpret_cast<const float4*>(weight + i);
        const float vs[4] = { v4.x, v4.y, v4.z, v4.w };
        #pragma unroll
        for (int q = 0; q < 4; ++q) {
            int e = i + q;
            int o = e / CK, r = e - o * CK;
            int c = r / 9, k = r - c * 9;
            g_whalf[o * CK + k * 256 + c] = __float2half_rn(vs[q]);
        }
    } else {
        // ---- womprep: womh[o][k*256+c] = w_om[o*2304 + c*9 + k], o<27 else 0 ----
        int i = (bid - 4672) * 256 + tid;       // < 73728 exactly
        int o = i / CK, r = i - o * CK;
        int k = r >> 8, c = r & 255;
        g_womh[i] = (o < 27) ? __float2half_rn(w_om[o * CK + c * 9 + k]) : __half(0.0f);
    }
}

// ---------------- kernel 2: offset-conv HMMA GEMM ------------------------------
// om[27, px] = w_om[27 x 2304] x im2col(x)[2304 x px].  B rows built on the fly
// from fp16 NHWC x: tap row = contiguous 64-ch chunk at shifted pixel (or zeros).
// grid 128 (one 128-px tile each), 256 threads (8 warps); warp tile 32(m) x 16(n).
__global__ void __launch_bounds__(256, 1)
offconv_kernel() {
    extern __shared__ __align__(16) char dyn_smem[];
    __shared__ int spx[K][128];                    // per-(tap, px) element offset or -1

    const uint32_t smem_base = smem_u32(dyn_smem);
    const uint32_t tile0 = (smem_base + 1023u) & ~1023u;

    const int tid  = threadIdx.x;
    const int wid  = tid >> 5;
    const int lane = tid & 31;
    const int pxb  = blockIdx.x << 7;              // 128 px per CTA
    const int b    = pxb >> 12;
    const int hwb  = pxb & 4095;

    // precompute per-px per-tap source offsets
    for (int i = tid; i < K * 128; i += 256) {
        int k = i >> 7, p = i & 127;
        int hw = hwb + p;
        int h = hw >> 6, w = hw & 63;
        int ky = k / 3 - 1, kx = k - (ky + 1) * 3 - 1;
        bool valid = ((unsigned)(h + ky) < H) && ((unsigned)(w + kx) < W);
        spx[k][p] = valid ? (((b << 12) + hw + ky * 64 + kx) << 8) : -1;
    }
    __syncthreads();

    const int rA = tid >> 3;      // 0..31
    const int sg = tid & 7;

    auto load_chunk = [&](int j) {
        int st = j % STG2;
        uint32_t sa = tile0 + st * STAGE2;         // A: 32 x 128B = 4KB
        uint32_t sb = sa + 4096;                   // B: 128 x 128B = 16KB
        int k  = j >> 2;
        int c0 = (j & 3) << 6;
        cp16(sa + sw128((uint32_t)(rA * 128 + sg * 16)), g_womh + rA * CK + k * 256 + c0 + sg * 8);
        #pragma unroll
        for (int q = 0; q < 4; ++q) {
            int idx = tid + (q << 8);
            int row = idx >> 3, s2 = idx & 7;
            int off = spx[k][row];
            const __half* src = (off >= 0) ? (g_xhalf + off + c0 + s2 * 8) : (g_zero + s2 * 8);
            cp16(sb + sw128((uint32_t)(row * 128 + s2 * 16)), src);
        }
        CP_COMMIT();
    };

    float acc[2][2][4];
    #pragma unroll
    for (int i = 0; i < 2; ++i)
        #pragma unroll
        for (int j = 0; j < 2; ++j)
            #pragma unroll
            for (int q = 0; q < 4; ++q) acc[i][j][q] = 0.0f;

    const uint32_t aRow = (uint32_t)(lane & 15);
    const uint32_t aCb  = (uint32_t)((lane >> 4) << 4);
    const uint32_t bRow = (uint32_t)(wid * 16 + ((lane >> 4) << 3) + (lane & 7));
    const uint32_t bCb  = (uint32_t)(((lane >> 3) & 1) << 4);

    load_chunk(0);
    load_chunk(1);
    load_chunk(2);

    for (int i = 0; i < NCH2; ++i) {
        CP_WAIT2();
        __syncthreads();
        if (i + STG2 - 1 < NCH2) load_chunk(i + STG2 - 1);

        int st = i % STG2;
        uint32_t sa = tile0 + st * STAGE2;
        uint32_t sb = sa + 4096;

        #pragma unroll
        for (int kk = 0; kk < 4; ++kk) {
            uint32_t a[2][4], bfr[2][2];
            #pragma unroll
            for (int mf = 0; mf < 2; ++mf)
                ldsm_x4(a[mf], sa + sw128((aRow + mf * 16) * 128 + aCb + kk * 32));
            {
                uint32_t r[4];
                ldsm_x4(r, sb + sw128(bRow * 128 + bCb + kk * 32));
                bfr[0][0] = r[0]; bfr[0][1] = r[1];
                bfr[1][0] = r[2]; bfr[1][1] = r[3];
            }
            #pragma unroll
            for (int mf = 0; mf < 2; ++mf)
                #pragma unroll
                for (int nf = 0; nf < 2; ++nf)
                    mma16816(acc[mf][nf], a[mf], bfr[nf]);
        }
    }
    CP_WAIT0();

    // epilogue: D[m=o][n=px] -> g_om[b][o][hw]
    const int nBase = hwb + wid * 16 + (lane & 3) * 2;
    #pragma unroll
    for (int mf = 0; mf < 2; ++mf) {
        int o0 = mf * 16 + (lane >> 2);
        int o8 = o0 + 8;
        #pragma unroll
        for (int nf = 0; nf < 2; ++nf) {
            int n = nBase + nf * 8;
            if (o0 < 27)
                *reinterpret_cast<float2*>(g_om + (b * 27 + o0) * HW + n) =
                    make_float2(acc[mf][nf][0], acc[mf][nf][1]);
            if (o8 < 27)
                *reinterpret_cast<float2*>(g_om + (b * 27 + o8) * HW + n) =
                    make_float2(acc[mf][nf][2], acc[mf][nf][3]);
        }
    }
}

// ---------------- kernel 3: fused params + gather (fp16 corner loads) ----------
// grid 2048, block 256 = 8 px. Phase 1: 72 threads compute the 8x9 sampling
// params into smem. Phase 2: warp = one pixel, lane = 4 channels (uint2 in/out).
__global__ void __launch_bounds__(256) gather_kernel(const float* __restrict__ b_om) {
    __shared__ float4 s_ww[8][9];
    __shared__ int4   s_cc[8][9];

    const int tid  = threadIdx.x;
    const int pix0 = blockIdx.x << 3;
    const int b    = pix0 >> 12;

    if (tid < 72) {
        const int p = tid / 9;
        const int k = tid - p * 9;
        const int hw = (pix0 + p) & 4095;
        const int h  = hw >> 6;
        const int w  = hw & 63;
        const float* omb = g_om + b * 27 * HW + hw;

        float off_y = omb[(2 * k    ) * HW] + b_om[2 * k];
        float off_x = omb[(2 * k + 1) * HW] + b_om[2 * k + 1];
        float mval  = omb[(18 + k   ) * HW] + b_om[18 + k];
        float m = 1.0f / (1.0f + expf(-mval));

        float py = (float)(h - 1 + k / 3) + off_y;
        float px = (float)(w - 1 + k % 3) + off_x;

        float y0f = floorf(py), x0f = floorf(px);
        float ly = py - y0f, lx = px - x0f;
        int y0 = (int)y0f, x0 = (int)x0f;
        int y1 = y0 + 1,   x1 = x0 + 1;

        float vy0 = (y0 >= 0 && y0 < H) ? 1.0f : 0.0f;
        float vy1 = (y1 >= 0 && y1 < H) ? 1.0f : 0.0f;
        float vx0 = (x0 >= 0 && x0 < W) ? 1.0f : 0.0f;
        float vx1 = (x1 >= 0 && x1 < W) ? 1.0f : 0.0f;

        float4 wv;
        wv.x = (1.0f - ly) * (1.0f - lx) * m * vy0 * vx0;
        wv.y = (1.0f - ly) * lx          * m * vy0 * vx1;
        wv.z = ly * (1.0f - lx)          * m * vy1 * vx0;
        wv.w = ly * lx                   * m * vy1 * vx1;

        int4 cv;
        cv.x = min(max(y0, 0), H - 1) * W;
        cv.y = min(max(y1, 0), H - 1) * W;
        cv.z = min(max(x0, 0), W - 1);
        cv.w = min(max(x1, 0), W - 1);

        s_ww[p][k] = wv;
        s_cc[p][k] = cv;
    }
    __syncthreads();

    const int wid  = tid >> 5;
    const int lane = tid & 31;
    const int px   = pix0 + wid;

    // fp16 corners: uint2 = 4 halves; pixel stride = 256 halves = 64 uint2
    const uint2* xb = reinterpret_cast<const uint2*>(g_xhalf) + ((size_t)b << 18);
    uint2* outp = reinterpret_cast<uint2*>(g_cols + (size_t)px * CK);

    #pragma unroll
    for (int k = 0; k < K; ++k) {
        const float4 ww = s_ww[wid][k];
        const int4   cc = s_cc[wid][k];
        const int p00 = (cc.x + cc.z) << 6;
        const int p01 = (cc.x + cc.w) << 6;
        const int p10 = (cc.y + cc.z) << 6;
        const int p11 = (cc.y + cc.w) << 6;
        #pragma unroll
        for (int it = 0; it < 2; ++it) {
            const int c4 = (it << 5) + lane;   // uint2 index: channels 4*c4..4*c4+3
            uint2 u00 = xb[p00 + c4], u01 = xb[p01 + c4];
            uint2 u10 = xb[p10 + c4], u11 = xb[p11 + c4];
            float2 f00a = __half22float2(*reinterpret_cast<__half2*>(&u00.x));
            float2 f00b = __half22float2(*reinterpret_cast<__half2*>(&u00.y));
            float2 f01a = __half22float2(*reinterpret_cast<__half2*>(&u01.x));
            float2 f01b = __half22float2(*reinterpret_cast<__half2*>(&u01.y));
            float2 f10a = __half22float2(*reinterpret_cast<__half2*>(&u10.x));
            float2 f10b = __half22float2(*reinterpret_cast<__half2*>(&u10.y));
            float2 f11a = __half22float2(*reinterpret_cast<__half2*>(&u11.x));
            float2 f11b = __half22float2(*reinterpret_cast<__half2*>(&u11.y));
            float va = ww.x * f00a.x + ww.y * f01a.x + ww.z * f10a.x + ww.w * f11a.x;
            float vb = ww.x * f00a.y + ww.y * f01a.y + ww.z * f10a.y + ww.w * f11a.y;
            float vc = ww.x * f00b.x + ww.y * f01b.x + ww.z * f10b.x + ww.w * f11b.x;
            float vd = ww.x * f00b.y + ww.y * f01b.y + ww.z * f10b.y + ww.w * f11b.y;
            __half2 h2a = __floats2half2_rn(va, vb);
            __half2 h2b = __floats2half2_rn(vc, vd);
            uint2 st;
            st.x = *reinterpret_cast<uint32_t*>(&h2a);
            st.y = *reinterpret_cast<uint32_t*>(&h2b);
            outp[k * 64 + c4] = st;
        }
    }
}

// ---------------- kernel 4: HMMA GEMM  D[o, px] = Whalf x Cols^T ---------------
// grid (2, 128): tile 128(o) x 128(px), 256 CTAs, occupancy 2.
// 8 warps as 2(m) x 4(n); warp tile 64 x 32. 3-stage cp.async, K = 2304 fp16.
__global__ void __launch_bounds__(256, 2)
gemm_kernel(const float* __restrict__ bias, float* __restrict__ out) {
    extern __shared__ __align__(16) char dyn_smem[];
    const uint32_t smem_base = smem_u32(dyn_smem);
    const uint32_t tile0 = (smem_base + 1023u) & ~1023u;

    const int tid  = threadIdx.x;
    const int wid  = tid >> 5;
    const int lane = tid & 31;
    const int o_tile = blockIdx.x;            // 0..1 (fast dim: same-px pair adjacent)
    const int pxb    = blockIdx.y << 7;       // 128 px per CTA

    const int wm = wid & 1;                   // m offset 64*wm
    const int wn = wid >> 1;                  // n offset 32*wn

    const __half* wA = g_whalf + (size_t)o_tile * 128 * CK;
    const __half* cB = g_cols + (size_t)pxb * CK;

    const int r0 = tid >> 3;                  // 0..31
    const int sg = tid & 7;

    auto load_chunk = [&](int j) {
        int st = j % STG;
        uint32_t sa = tile0 + st * STAGE_BYTES;
        uint32_t sb = sa + 16384;
        int koff = j * KC + sg * 8;
        #pragma unroll
        for (int q = 0; q < 4; ++q) {        // A: 128 rows
            int r = r0 + (q << 5);
            cp16(sa + sw128((uint32_t)(r * 128 + sg * 16)), wA + (size_t)r * CK + koff);
        }
        #pragma unroll
        for (int q = 0; q < 4; ++q) {        // B: 128 rows
            int r = r0 + (q << 5);
            cp16(sb + sw128((uint32_t)(r * 128 + sg * 16)), cB + (size_t)r * CK + koff);
        }
        CP_COMMIT();
    };

    float acc[4][4][4];
    #pragma unroll
    for (int i = 0; i < 4; ++i)
        #pragma unroll
        for (int j = 0; j < 4; ++j)
            #pragma unroll
            for (int q = 0; q < 4; ++q) acc[i][j][q] = 0.0f;

    const uint32_t aRow = (uint32_t)(wm * 64 + (lane & 15));
    const uint32_t aCb  = (uint32_t)((lane >> 4) << 4);
    const uint32_t bRow = (uint32_t)(wn * 32 + ((lane >> 4) << 3) + (lane & 7));
    const uint32_t bCb  = (uint32_t)(((lane >> 3) & 1) << 4);

    load_chunk(0);
    load_chunk(1);

    for (int i = 0; i < NCHUNK; ++i) {
        if (i + 1 < NCHUNK) CP_WAIT1(); else CP_WAIT0();
        __syncthreads();
        if (i + STG - 1 < NCHUNK) load_chunk(i + STG - 1);

        int st = i % STG;
        uint32_t sa = tile0 + st * STAGE_BYTES;
        uint32_t sb = sa + 16384;

        #pragma unroll
        for (int kk = 0; kk < 4; ++kk) {
            uint32_t a[4][4], b[4][2];
            #pragma unroll
            for (int mf = 0; mf < 4; ++mf)
                ldsm_x4(a[mf], sa + sw128((aRow + mf * 16) * 128 + aCb + kk * 32));
            #pragma unroll
            for (int half = 0; half < 2; ++half) {
                uint32_t r[4];
                ldsm_x4(r, sb + sw128((bRow + half * 16) * 128 + bCb + kk * 32));
                b[2 * half][0] = r[0]; b[2 * half][1] = r[1];
                b[2 * half + 1][0] = r[2]; b[2 * half + 1][1] = r[3];
            }
            #pragma unroll
            for (int mf = 0; mf < 4; ++mf)
                #pragma unroll
                for (int nf = 0; nf < 4; ++nf)
                    mma16816(acc[mf][nf], a[mf], b[nf]);
        }
    }
    CP_WAIT0();

    // ---- epilogue: direct register -> gmem stores -----------------------------
    const int bb  = pxb >> 12;
    const int hw0 = pxb & 4095;
    const int oBase = o_tile * 128 + wm * 64 + (lane >> 2);
    const int nBase = hw0 + wn * 32 + (lane & 3) * 2;

    #pragma unroll
    for (int mf = 0; mf < 4; ++mf) {
        int o0 = oBase + mf * 16;
        float bz0 = __ldg(bias + o0);
        float bz8 = __ldg(bias + o0 + 8);
        float* op0 = out + (bb << 20) + (o0 << 12) + nBase;
        float* op8 = op0 + (8 << 12);
        #pragma unroll
        for (int nf = 0; nf < 4; ++nf) {
            float2 v0 = make_float2(acc[mf][nf][0] + bz0, acc[mf][nf][1] + bz0);
            float2 v1 = make_float2(acc[mf][nf][2] + bz8, acc[mf][nf][3] + bz8);
            *reinterpret_cast<float2*>(op0 + nf * 8) = v0;
            *reinterpret_cast<float2*>(op8 + nf * 8) = v1;
        }
    }
}

// ---------------- launch ------------------------------------------------------
extern "C" void kernel_launch(void* const* d_in, const int* in_sizes, int n_in,
                              void* d_out, int out_size) {
    const float* x      = (const float*)d_in[0];   // (4,256,64,64)
    const float* w_om   = (const float*)d_in[1];   // (27,256,3,3)
    const float* b_om   = (const float*)d_in[2];   // (27,)
    const float* weight = (const float*)d_in[3];   // (256,256,3,3)
    const float* bias   = (const float*)d_in[4];   // (256,)
    float* out = (float*)d_out;                    // (4,256,64,64)

    cudaFuncSetAttribute(offconv_kernel, cudaFuncAttributeMaxDynamicSharedMemorySize, SMEM2);
    cudaFuncSetAttribute(gemm_kernel, cudaFuncAttributeMaxDynamicSharedMemorySize, SMEM_DYN);

    prep_kernel<<<4960, 256>>>(x, w_om, weight);
    offconv_kernel<<<128, 256, SMEM2>>>();
    gather_kernel<<<2048, 256>>>(b_om);
    gemm_kernel<<<dim3(2, 128), 256, SMEM_DYN>>>(bias, out);
}